// round 13
// baseline (speedup 1.0000x reference)
#include <cuda_runtime.h>
#include <cstdint>
#include <math.h>

// ---------------------------------------------------------------------------
// UNet4LMCD round 12: R11 (PDL chain, LDS.128 weights, FFMA2) +
//  - tconv: single-chunk weight staging (no chunk loop; Cin<=64 in smem)
//  - tconv: cl-loop unroll 2 (double input-load MLP in the dominant kernels)
// ---------------------------------------------------------------------------

#define V0_ (128*128*128)
#define V1_ (64*64*64)
#define V2_ (32*32*32)
#define V3_ (16*16*16)
#define PMAX_ 2048

typedef unsigned long long ull;

__device__ float   g_s8  [64 * V3_];
__device__ float   g_cat2[64 * V2_];          // [tconv3 out (32) | s4 (32)]
__device__ float   g_cat1[48 * V1_];          // [tconv2 out (32) | s2 (16)]
__device__ float   g_cat0[32u * V0_];         // [tconv1 out (24) | s1 (8)]
__device__ double2 g_part[64 * PMAX_];
__device__ float2  g_coef0[32];
__device__ float2  g_coef1[48];
__device__ float2  g_coef2[64];
__device__ float2  g_coefs8[64];

// ---- PDL device helpers -----------------------------------------------------
__device__ __forceinline__ void pdl_sync()    { cudaGridDependencySynchronize(); }
__device__ __forceinline__ void pdl_trigger() { cudaTriggerProgrammaticLaunchCompletion(); }

// ---- packed f32x2 helpers --------------------------------------------------
__device__ __forceinline__ ull pack2(float lo, float hi) {
    ull r;
    asm("mov.b64 %0, {%1, %2};" : "=l"(r) : "f"(lo), "f"(hi));
    return r;
}
__device__ __forceinline__ ull fma2(ull a, ull b, ull c) {
    ull d;
    asm("fma.rn.f32x2 %0, %1, %2, %3;" : "=l"(d) : "l"(a), "l"(b), "l"(c));
    return d;
}
__device__ __forceinline__ float2 unpack2(ull v) {
    float2 f;
    asm("mov.b64 {%0, %1}, %2;" : "=f"(f.x), "=f"(f.y) : "l"(v));
    return f;
}
__device__ __forceinline__ ull ld64(const float2* p) {
    return *reinterpret_cast<const ull*>(p);
}
__device__ __forceinline__ void ld128(const float2* p, ull& a, ull& b) {
    const ulonglong2 v = *reinterpret_cast<const ulonglong2*>(p);
    a = v.x; b = v.y;
}
__device__ __forceinline__ float bnr(float v, float2 c) {
    return fmaxf(fmaf(v, c.x, c.y), 0.f);
}

// ---------------------------------------------------------------------------
// Fused BN-stats epilogue over flattened accumulators acc[CG][NT].
// ---------------------------------------------------------------------------
template <int CG, int NT>
__device__ __forceinline__ void stats_epilogue(const float (*acc)[NT],
                                               double2* __restrict__ part,
                                               int cb, int tid, int nthr) {
    float s[CG], q[CG];
#pragma unroll
    for (int g = 0; g < CG; g++) {
        float ss = 0.f, qq = 0.f;
#pragma unroll
        for (int t = 0; t < NT; t++) {
            ss += acc[g][t];
            qq = fmaf(acc[g][t], acc[g][t], qq);
        }
        s[g] = ss; q[g] = qq;
    }
#pragma unroll
    for (int o = 16; o > 0; o >>= 1) {
#pragma unroll
        for (int g = 0; g < CG; g++) {
            s[g] += __shfl_down_sync(0xffffffffu, s[g], o);
            q[g] += __shfl_down_sync(0xffffffffu, q[g], o);
        }
    }
    __shared__ float2 red[CG][8];
    const int wid = tid >> 5, lane = tid & 31;
    if (lane == 0) {
#pragma unroll
        for (int g = 0; g < CG; g++) red[g][wid] = make_float2(s[g], q[g]);
    }
    __syncthreads();
    const int nw = nthr >> 5;
    if (tid < CG) {
        double ds = 0.0, dq = 0.0;
        for (int w = 0; w < nw; w++) {
            ds += (double)red[tid][w].x;
            dq += (double)red[tid][w].y;
        }
        const int pidx = blockIdx.x + gridDim.x * blockIdx.y;
        part[(size_t)(cb + tid) * PMAX_ + pidx] = make_double2(ds, dq);
    }
}

// ---------------------------------------------------------------------------
// Stride-1 3x3x3 conv, packed: CG x TZ x TX(=8). Padded weight layout:
// 4 float2 per (g,ci,kd,kh) triplet -> (w0,w1) via LDS.128, w2 via LDS.64.
// ---------------------------------------------------------------------------
template <int CG, int TZ, int TX, bool STATS, bool APPLY>
__global__ void __launch_bounds__(128) conv_s1_kernel(
        const float* __restrict__ in, const float* __restrict__ wt,
        const float2* __restrict__ coef,
        float* __restrict__ out, double2* __restrict__ part,
        int Cin, int D, int H, int W) {
    static_assert(TX == 8, "conv_s1 needs TX==8");
    extern __shared__ __align__(16) float2 sw2[];
    const int cb   = blockIdx.z * CG;
    const int tid  = threadIdx.y * blockDim.x + threadIdx.x;
    const int nthr = blockDim.x * blockDim.y;
    for (int i = tid; i < CG * Cin * 27; i += nthr) {
        const float w = wt[(size_t)cb * Cin * 27 + i];
        const int tri = i / 3, t = i - tri * 3;
        sw2[tri * 4 + t] = make_float2(w, w);
    }
    __syncthreads();
    pdl_sync();                 // predecessor data (in, coef) needed below

    const int x0 = threadIdx.x * TX;
    const int y  = blockIdx.x * blockDim.y + threadIdx.y;
    const int z0 = blockIdx.y * TZ;

    ull accp[CG][TZ][TX / 2];
#pragma unroll
    for (int g = 0; g < CG; g++)
#pragma unroll
        for (int zz = 0; zz < TZ; zz++)
#pragma unroll
            for (int k = 0; k < TX / 2; k++) accp[g][zz][k] = 0ull;

    for (int ci = 0; ci < Cin; ci++) {
        const float* inc = in + (size_t)ci * D * H * W;
        float2 cf = APPLY ? coef[ci] : make_float2(1.f, 0.f);
#pragma unroll
        for (int pz = 0; pz < TZ + 2; pz++) {
            const int iz = z0 - 1 + pz;
            if (iz < 0 || iz >= D) continue;
#pragma unroll
            for (int kh = 0; kh < 3; kh++) {
                const int iy = y + kh - 1;
                if (iy < 0 || iy >= H) continue;
                const float* row = inc + ((size_t)iz * H + iy) * W;
                float r[TX + 2];
                const float4 v0 = *reinterpret_cast<const float4*>(row + x0);
                const float4 v1 = *reinterpret_cast<const float4*>(row + x0 + 4);
                if (APPLY) {
                    r[0] = (x0 > 0) ? bnr(row[x0 - 1], cf) : 0.f;
                    r[1] = bnr(v0.x, cf); r[2] = bnr(v0.y, cf);
                    r[3] = bnr(v0.z, cf); r[4] = bnr(v0.w, cf);
                    r[5] = bnr(v1.x, cf); r[6] = bnr(v1.y, cf);
                    r[7] = bnr(v1.z, cf); r[8] = bnr(v1.w, cf);
                    r[9] = (x0 + TX < W) ? bnr(row[x0 + TX], cf) : 0.f;
                } else {
                    r[0] = (x0 > 0) ? row[x0 - 1] : 0.f;
                    r[1] = v0.x; r[2] = v0.y; r[3] = v0.z; r[4] = v0.w;
                    r[5] = v1.x; r[6] = v1.y; r[7] = v1.z; r[8] = v1.w;
                    r[9] = (x0 + TX < W) ? row[x0 + TX] : 0.f;
                }
                // pair registers: E_k = (r[2k], r[2k+1]), O_k = (r[2k+1], r[2k+2])
                ull E[TX / 2 + 1], O[TX / 2];
#pragma unroll
                for (int k = 0; k <= TX / 2; k++) E[k] = pack2(r[2 * k], r[2 * k + 1]);
#pragma unroll
                for (int k = 0; k < TX / 2; k++)  O[k] = pack2(r[2 * k + 1], r[2 * k + 2]);
#pragma unroll
                for (int zz = 0; zz < TZ; zz++) {
                    const int kd = iz - (z0 + zz) + 1;
                    if (kd < 0 || kd > 2) continue;
#pragma unroll
                    for (int g = 0; g < CG; g++) {
                        const float2* wp = sw2 +
                            (((size_t)g * Cin + ci) * 9 + kd * 3 + kh) * 4;
                        ull w0, w1; ld128(wp, w0, w1);
                        const ull w2 = ld64(wp + 2);
#pragma unroll
                        for (int k = 0; k < TX / 2; k++)
                            accp[g][zz][k] = fma2(E[k], w0,
                                             fma2(O[k], w1,
                                             fma2(E[k + 1], w2, accp[g][zz][k])));
                    }
                }
            }
        }
    }
    pdl_trigger();              // successor may launch; epilogue remains

#pragma unroll
    for (int g = 0; g < CG; g++)
#pragma unroll
        for (int zz = 0; zz < TZ; zz++) {
            float* orow = out + (((size_t)(cb + g) * D + z0 + zz) * H + y) * W + x0;
#pragma unroll
            for (int k = 0; k < TX / 2; k += 2) {
                const float2 a = unpack2(accp[g][zz][k]);
                const float2 b = unpack2(accp[g][zz][k + 1]);
                *reinterpret_cast<float4*>(orow + 2 * k) = make_float4(a.x, a.y, b.x, b.y);
            }
        }
    if (STATS) {
        float acc_f[CG][TZ * TX];
#pragma unroll
        for (int g = 0; g < CG; g++)
#pragma unroll
            for (int zz = 0; zz < TZ; zz++)
#pragma unroll
                for (int k = 0; k < TX / 2; k++) {
                    const float2 a = unpack2(accp[g][zz][k]);
                    acc_f[g][zz * TX + 2 * k]     = a.x;
                    acc_f[g][zz * TX + 2 * k + 1] = a.y;
                }
        stats_epilogue<CG, TZ * TX>(acc_f, part, cb, tid, nthr);
    }
}

// ---------------------------------------------------------------------------
// Stride-2 3x3x3 conv, packed: CG x TX (2 or 4). Padded weight layout.
// ---------------------------------------------------------------------------
template <int CG, int TX, bool STATS>
__global__ void conv_s2_kernel(
        const float* __restrict__ in, const float* __restrict__ wt,
        const float2* __restrict__ coef,
        float* __restrict__ out, double2* __restrict__ part,
        int Cin, int Di, int Hi, int Wi, int Do, int Ho, int Wo) {
    static_assert(TX == 2 || TX == 4, "conv_s2 needs TX in {2,4}");
    extern __shared__ __align__(16) float2 sw2[];
    const int cb   = blockIdx.z * CG;
    const int tid  = threadIdx.y * blockDim.x + threadIdx.x;
    const int nthr = blockDim.x * blockDim.y;
    for (int i = tid; i < CG * Cin * 27; i += nthr) {
        const float w = wt[(size_t)cb * Cin * 27 + i];
        const int tri = i / 3, t = i - tri * 3;
        sw2[tri * 4 + t] = make_float2(w, w);
    }
    __syncthreads();
    pdl_sync();

    const int x0 = threadIdx.x * TX;
    const int bx = 2 * x0;
    const int y  = blockIdx.x * blockDim.y + threadIdx.y;
    const int z  = blockIdx.y;

    ull accp[CG][TX / 2];
#pragma unroll
    for (int g = 0; g < CG; g++)
#pragma unroll
        for (int k = 0; k < TX / 2; k++) accp[g][k] = 0ull;

    for (int ci = 0; ci < Cin; ci++) {
        const float* inc = in + (size_t)ci * Di * Hi * Wi;
        const float2 cf = coef[ci];
#pragma unroll
        for (int kd = 0; kd < 3; kd++) {
            const int iz = 2 * z + kd - 1;
            if (iz < 0 || iz >= Di) continue;
#pragma unroll
            for (int kh = 0; kh < 3; kh++) {
                const int iy = 2 * y + kh - 1;
                if (iy < 0 || iy >= Hi) continue;
                const float* row = inc + ((size_t)iz * Hi + iy) * Wi;
                float rr[2 * TX + 2];
                rr[0] = (bx > 0) ? bnr(row[bx - 1], cf) : 0.f;
#pragma unroll
                for (int q = 0; q < TX / 2; q++) {
                    const float4 v = *reinterpret_cast<const float4*>(row + bx + 4 * q);
                    rr[4 * q + 1] = bnr(v.x, cf); rr[4 * q + 2] = bnr(v.y, cf);
                    rr[4 * q + 3] = bnr(v.z, cf); rr[4 * q + 4] = bnr(v.w, cf);
                }
                rr[2 * TX + 1] = (bx + 2 * TX < Wi) ? bnr(row[bx + 2 * TX], cf) : 0.f;
                ull M[3][TX / 2];
#pragma unroll
                for (int j = 0; j < 3; j++)
#pragma unroll
                    for (int k = 0; k < TX / 2; k++)
                        M[j][k] = pack2(rr[4 * k + j], rr[4 * k + j + 2]);
#pragma unroll
                for (int g = 0; g < CG; g++) {
                    const float2* wp = sw2 +
                        (((size_t)g * Cin + ci) * 9 + kd * 3 + kh) * 4;
                    ull w0, w1; ld128(wp, w0, w1);
                    const ull w2 = ld64(wp + 2);
#pragma unroll
                    for (int k = 0; k < TX / 2; k++)
                        accp[g][k] = fma2(M[0][k], w0,
                                     fma2(M[1][k], w1,
                                     fma2(M[2][k], w2, accp[g][k])));
                }
            }
        }
    }
    pdl_trigger();

#pragma unroll
    for (int g = 0; g < CG; g++) {
        float* orow = out + (((size_t)(cb + g) * Do + z) * Ho + y) * Wo + x0;
        if constexpr (TX == 2) {
            *reinterpret_cast<float2*>(orow) = unpack2(accp[g][0]);
        } else {
            const float2 a = unpack2(accp[g][0]);
            const float2 b = unpack2(accp[g][1]);
            *reinterpret_cast<float4*>(orow) = make_float4(a.x, a.y, b.x, b.y);
        }
    }
    if (STATS) {
        float acc_f[CG][TX];
#pragma unroll
        for (int g = 0; g < CG; g++)
#pragma unroll
            for (int k = 0; k < TX / 2; k++) {
                const float2 a = unpack2(accp[g][k]);
                acc_f[g][2 * k] = a.x; acc_f[g][2 * k + 1] = a.y;
            }
        stats_epilogue<CG, TX>(acc_f, part, cb, tid, nthr);
    }
}

// ---------------------------------------------------------------------------
// Stride-2 transposed conv, packed y-pair tile, TX in {4,8}.
// SINGLE-CHUNK weight staging (Cin <= 64 fits smem). cl loop unrolled 2x to
// double input-load MLP.
// ---------------------------------------------------------------------------
template <int CG, int TX, bool STATS>
__global__ void tconv_kernel(
        const float* __restrict__ in, const float* __restrict__ wt,
        const float2* __restrict__ coef,
        float* __restrict__ out, double2* __restrict__ part,
        int Cin, int Di, int Hi, int Wi) {
    static_assert(TX == 4 || TX == 8, "tconv needs TX in {4,8}");
    const int Do = 2 * Di, Ho = 2 * Hi, Wo = 2 * Wi;
    extern __shared__ __align__(16) float2 sw2[];
    const int cb   = blockIdx.z * CG;
    const int tid  = threadIdx.y * blockDim.x + threadIdx.x;
    const int nthr = blockDim.x * blockDim.y;

    const int x0 = threadIdx.x * TX;
    const int i0 = x0 >> 1;
    const int yp = blockIdx.x * blockDim.y + threadIdx.y;
    const int z  = blockIdx.y;

    ull accpE[CG][TX / 2], accpO[CG][TX / 2];
#pragma unroll
    for (int g = 0; g < CG; g++)
#pragma unroll
        for (int k = 0; k < TX / 2; k++) { accpE[g][k] = 0ull; accpO[g][k] = 0ull; }

    const bool hb = (yp + 1 < Hi);
    const bool xe = (i0 + TX / 2 < Wi);

    // single-chunk staging: 6 float2 per (g, cl, kd)
    for (int i = tid; i < CG * Cin * 3; i += nthr) {
        const int g   = i / (Cin * 3);
        const int rem = i - g * (Cin * 3);
        const int cl  = rem / 3;
        const int kd  = rem - cl * 3;
        const float* w = wt + ((size_t)(cb + g) * Cin + cl) * 27 + kd * 9;
        float2* p = sw2 + (size_t)i * 6;
        p[0] = make_float2(w[4], w[3]);   // (wa1, wa0)  kh=1
        p[1] = make_float2(0.f,  w[5]);   // (0,   wa2)
        p[2] = make_float2(w[1], w[0]);   // (wb1, wb0)  kh=0
        p[3] = make_float2(w[7], w[6]);   // (wc1, wc0)  kh=2
        p[4] = make_float2(0.f,  w[2]);   // (0,   wb2)
        p[5] = make_float2(0.f,  w[8]);   // (0,   wc2)
    }
    __syncthreads();
    pdl_sync();

#pragma unroll 2
    for (int cl = 0; cl < Cin; cl++) {
        const float* inc = in + (size_t)cl * Di * Hi * Wi;
        const float2 cf = coef[cl];
#pragma unroll
        for (int kd = 0; kd < 3; kd++) {
            const int dz = z - 1 + kd;
            if (dz < 0 || (dz & 1)) continue;
            const int iz = dz >> 1;
            if (iz >= Di) continue;

            const float* prow = inc + ((size_t)iz * Hi + yp) * Wi;
            float r[TX / 2 + 1], s[TX / 2 + 1];
            if constexpr (TX == 8) {
                const float4 v = *reinterpret_cast<const float4*>(prow + i0);
                r[0] = bnr(v.x, cf); r[1] = bnr(v.y, cf);
                r[2] = bnr(v.z, cf); r[3] = bnr(v.w, cf);
                r[4] = xe ? bnr(prow[i0 + 4], cf) : 0.f;
            } else {
                const float2 v = *reinterpret_cast<const float2*>(prow + i0);
                r[0] = bnr(v.x, cf); r[1] = bnr(v.y, cf);
                r[2] = xe ? bnr(prow[i0 + 2], cf) : 0.f;
            }
            if (hb) {
                const float* qrow = prow + Wi;
                if constexpr (TX == 8) {
                    const float4 u = *reinterpret_cast<const float4*>(qrow + i0);
                    s[0] = bnr(u.x, cf); s[1] = bnr(u.y, cf);
                    s[2] = bnr(u.z, cf); s[3] = bnr(u.w, cf);
                    s[4] = xe ? bnr(qrow[i0 + 4], cf) : 0.f;
                } else {
                    const float2 u = *reinterpret_cast<const float2*>(qrow + i0);
                    s[0] = bnr(u.x, cf); s[1] = bnr(u.y, cf);
                    s[2] = xe ? bnr(qrow[i0 + 2], cf) : 0.f;
                }
            } else {
#pragma unroll
                for (int e = 0; e <= TX / 2; e++) s[e] = 0.f;
            }
            ull rb[TX / 2 + 1], sb[TX / 2 + 1];
#pragma unroll
            for (int e = 0; e <= TX / 2; e++) {
                rb[e] = pack2(r[e], r[e]);
                sb[e] = pack2(s[e], s[e]);
            }
#pragma unroll
            for (int g = 0; g < CG; g++) {
                const float2* p = sw2 + ((size_t)(g * Cin + cl) * 3 + kd) * 6;
                ull p0, p1; ld128(p,     p0, p1);
                ull p2, p3; ld128(p + 2, p2, p3);
                ull p4, p5; ld128(p + 4, p4, p5);
#pragma unroll
                for (int e = 0; e < TX / 2; e++) {
                    accpE[g][e] = fma2(rb[e], p0, fma2(rb[e + 1], p1, accpE[g][e]));
                    accpO[g][e] = fma2(rb[e], p2,
                                  fma2(sb[e], p3,
                                  fma2(rb[e + 1], p4,
                                  fma2(sb[e + 1], p5, accpO[g][e]))));
                }
            }
        }
    }
    pdl_trigger();

#pragma unroll
    for (int g = 0; g < CG; g++) {
        float* erow = out + (((size_t)(cb + g) * Do + z) * Ho + 2 * yp) * Wo + x0;
        float* orow = erow + Wo;
#pragma unroll
        for (int k = 0; k < TX / 2; k += 2) {
            const float2 a = unpack2(accpE[g][k]);
            const float2 b = unpack2(accpE[g][k + 1]);
            *reinterpret_cast<float4*>(erow + 2 * k) = make_float4(a.x, a.y, b.x, b.y);
            const float2 c = unpack2(accpO[g][k]);
            const float2 d = unpack2(accpO[g][k + 1]);
            *reinterpret_cast<float4*>(orow + 2 * k) = make_float4(c.x, c.y, d.x, d.y);
        }
    }
    if (STATS) {
        float acc_f[CG][2 * TX];
#pragma unroll
        for (int g = 0; g < CG; g++)
#pragma unroll
            for (int k = 0; k < TX / 2; k++) {
                const float2 a = unpack2(accpE[g][k]);
                const float2 b = unpack2(accpO[g][k]);
                acc_f[g][2 * k]          = a.x;
                acc_f[g][2 * k + 1]      = a.y;
                acc_f[g][TX + 2 * k]     = b.x;
                acc_f[g][TX + 2 * k + 1] = b.y;
            }
        stats_epilogue<CG, 2 * TX>(acc_f, part, cb, tid, nthr);
    }
}

// ---------------------------------------------------------------------------
// BN finalize: partials -> per-channel (a, b) coefficients. Syncs at entry,
// triggers immediately so the next conv stages weights during the finalize.
// ---------------------------------------------------------------------------
__global__ void bn_finalize(const double2* __restrict__ part,
                            float2* __restrict__ coef,
                            const float* __restrict__ gam,
                            const float* __restrict__ bet,
                            int P, int V, float eps) {
    pdl_sync();
    pdl_trigger();
    const int c = blockIdx.x;
    double s = 0.0, q = 0.0;
    for (int i = threadIdx.x; i < P; i += 256) {
        const double2 pp = part[(size_t)c * PMAX_ + i];
        s += pp.x; q += pp.y;
    }
    __shared__ double ss[256], sq[256];
    ss[threadIdx.x] = s; sq[threadIdx.x] = q;
    __syncthreads();
    for (int o = 128; o > 0; o >>= 1) {
        if (threadIdx.x < o) {
            ss[threadIdx.x] += ss[threadIdx.x + o];
            sq[threadIdx.x] += sq[threadIdx.x + o];
        }
        __syncthreads();
    }
    if (threadIdx.x == 0) {
        const double mean = ss[0] / V;
        const double var  = sq[0] / V - mean * mean;
        const float inv_std = (float)(1.0 / sqrt(var + (double)eps));
        const float a = inv_std * gam[c];
        const float b = fmaf(-(float)mean, a, bet[c]);
        coef[c] = make_float2(a, b);
    }
}

// ---------------------------------------------------------------------------
// Host orchestration — all launches via cudaLaunchKernelEx with PDL.
// ---------------------------------------------------------------------------
extern "C" void kernel_launch(void* const* d_in, const int* in_sizes, int n_in,
                              void* d_out, int out_size) {
    (void)in_sizes; (void)n_in; (void)out_size;

    const float* x     = (const float*)d_in[0];
    const float* w0    = (const float*)d_in[1];
    const float* g0    = (const float*)d_in[2];
    const float* b0    = (const float*)d_in[3];
    const float* w1    = (const float*)d_in[4];
    const float* g1    = (const float*)d_in[5];
    const float* b1    = (const float*)d_in[6];
    const float* w2    = (const float*)d_in[7];
    const float* g2    = (const float*)d_in[8];
    const float* b2    = (const float*)d_in[9];
    const float* w3    = (const float*)d_in[10];
    const float* g3    = (const float*)d_in[11];
    const float* b3    = (const float*)d_in[12];
    const float* wt3   = (const float*)d_in[13];
    const float* gt3   = (const float*)d_in[14];
    const float* bt3   = (const float*)d_in[15];
    const float* wt2   = (const float*)d_in[16];
    const float* gt2   = (const float*)d_in[17];
    const float* bt2   = (const float*)d_in[18];
    const float* wt1   = (const float*)d_in[19];
    const float* gt1   = (const float*)d_in[20];
    const float* bt1   = (const float*)d_in[21];
    const float* w_out = (const float*)d_in[22];

    float *cat0, *cat1, *cat2, *s8;
    double2* part;
    float2 *coef0, *coef1, *coef2, *coefs8;
    cudaGetSymbolAddress((void**)&cat0,   g_cat0);
    cudaGetSymbolAddress((void**)&cat1,   g_cat1);
    cudaGetSymbolAddress((void**)&cat2,   g_cat2);
    cudaGetSymbolAddress((void**)&s8,     g_s8);
    cudaGetSymbolAddress((void**)&part,   g_part);
    cudaGetSymbolAddress((void**)&coef0,  g_coef0);
    cudaGetSymbolAddress((void**)&coef1,  g_coef1);
    cudaGetSymbolAddress((void**)&coef2,  g_coef2);
    cudaGetSymbolAddress((void**)&coefs8, g_coefs8);

    float* s1 = cat0 + (size_t)24 * V0_;
    float* s2 = cat1 + (size_t)32 * V1_;
    float* s4 = cat2 + (size_t)32 * V2_;

    cudaLaunchAttribute pdl_attr[1];
    pdl_attr[0].id = cudaLaunchAttributeProgrammaticStreamSerialization;
    pdl_attr[0].val.programmaticStreamSerializationAllowed = 1;

    auto cfg = [&](dim3 g, dim3 b, size_t smem) {
        cudaLaunchConfig_t c = {};
        c.gridDim = g; c.blockDim = b; c.dynamicSmemBytes = smem;
        c.stream = 0; c.attrs = pdl_attr; c.numAttrs = 1;
        return c;
    };

    // ---- encoder ----
    // conv0: 8->8, 128^3, stride 1 (raw input)
    {
        cudaLaunchConfig_t c = cfg(dim3(16, 128, 1), dim3(16, 8), 8 * 8 * 9 * 4 * 8);
        cudaLaunchKernelEx(&c, conv_s1_kernel<8, 1, 8, true, false>,
            x, w0, (const float2*)nullptr, s1, part, 8, 128, 128, 128);
    }
    {
        cudaLaunchConfig_t c = cfg(dim3(8, 1, 1), dim3(256, 1, 1), 0);
        cudaLaunchKernelEx(&c, bn_finalize,
            (const double2*)part, coef0 + 24, g0, b0, 16 * 128, V0_, 1e-5f);
    }

    // conv1: 8->16, stride 2 -> 64^3
    {
        cudaLaunchConfig_t c = cfg(dim3(8, 64, 2), dim3(16, 8), 8 * 8 * 9 * 4 * 8);
        cudaLaunchKernelEx(&c, conv_s2_kernel<8, 4, true>,
            (const float*)s1, w1, (const float2*)(coef0 + 24), s2, part,
            8, 128, 128, 128, 64, 64, 64);
    }
    {
        cudaLaunchConfig_t c = cfg(dim3(16, 1, 1), dim3(256, 1, 1), 0);
        cudaLaunchKernelEx(&c, bn_finalize,
            (const double2*)part, coef1 + 32, g1, b1, 8 * 64, V1_, 1e-5f);
    }

    // conv2: 16->32, stride 2 -> 32^3 (CG=4)
    {
        cudaLaunchConfig_t c = cfg(dim3(4, 32, 8), dim3(8, 8), 4 * 16 * 9 * 4 * 8);
        cudaLaunchKernelEx(&c, conv_s2_kernel<4, 4, true>,
            (const float*)s2, w2, (const float2*)(coef1 + 32), s4, part,
            16, 64, 64, 64, 32, 32, 32);
    }
    {
        cudaLaunchConfig_t c = cfg(dim3(32, 1, 1), dim3(256, 1, 1), 0);
        cudaLaunchKernelEx(&c, bn_finalize,
            (const double2*)part, coef2 + 32, g2, b2, 4 * 32, V2_, 1e-5f);
    }

    // conv3: 32->64, stride 2 -> 16^3 (CG=2, TX=2)
    {
        cudaLaunchConfig_t c = cfg(dim3(1, 16, 32), dim3(8, 16), 2 * 32 * 9 * 4 * 8);
        cudaLaunchKernelEx(&c, conv_s2_kernel<2, 2, true>,
            (const float*)s4, w3, (const float2*)(coef2 + 32), s8, part,
            32, 32, 32, 32, 16, 16, 16);
    }
    {
        cudaLaunchConfig_t c = cfg(dim3(64, 1, 1), dim3(256, 1, 1), 0);
        cudaLaunchKernelEx(&c, bn_finalize,
            (const double2*)part, coefs8, g3, b3, 1 * 16, V3_, 1e-5f);
    }

    // ---- decoder ----  (tconv smem: CG*Cin*3*6 float2)
    // tconv3: 64->32, 16^3 -> 32^3 (CG=2, TX=4)
    {
        cudaLaunchConfig_t c = cfg(dim3(2, 32, 16), dim3(8, 8), 2 * 64 * 3 * 6 * 8);
        cudaLaunchKernelEx(&c, tconv_kernel<2, 4, true>,
            (const float*)s8, wt3, (const float2*)coefs8, cat2, part,
            64, 16, 16, 16);
    }
    {
        cudaLaunchConfig_t c = cfg(dim3(32, 1, 1), dim3(256, 1, 1), 0);
        cudaLaunchKernelEx(&c, bn_finalize,
            (const double2*)part, coef2, gt3, bt3, 2 * 32, V2_, 1e-5f);
    }

    // tconv2: 64->32, 32^3 -> 64^3
    {
        cudaLaunchConfig_t c = cfg(dim3(2, 64, 8), dim3(8, 16), 4 * 64 * 3 * 6 * 8);
        cudaLaunchKernelEx(&c, tconv_kernel<4, 8, true>,
            (const float*)cat2, wt2, (const float2*)coef2, cat1, part,
            64, 32, 32, 32);
    }
    {
        cudaLaunchConfig_t c = cfg(dim3(32, 1, 1), dim3(256, 1, 1), 0);
        cudaLaunchKernelEx(&c, bn_finalize,
            (const double2*)part, coef1, gt2, bt2, 2 * 64, V1_, 1e-5f);
    }

    // tconv1: 48->24, 64^3 -> 128^3
    {
        cudaLaunchConfig_t c = cfg(dim3(8, 128, 6), dim3(16, 8), 4 * 48 * 3 * 6 * 8);
        cudaLaunchKernelEx(&c, tconv_kernel<4, 8, true>,
            (const float*)cat1, wt1, (const float2*)coef1, cat0, part,
            48, 64, 64, 64);
    }
    {
        cudaLaunchConfig_t c = cfg(dim3(24, 1, 1), dim3(256, 1, 1), 0);
        cudaLaunchKernelEx(&c, bn_finalize,
            (const double2*)part, coef0, gt1, bt1, 8 * 128, V0_, 1e-5f);
    }

    // conv_out: 32->2, 128^3, stride 1, TZ=2, folded BN on cat0 loads
    {
        cudaLaunchConfig_t c = cfg(dim3(16, 64, 1), dim3(16, 8), 2 * 32 * 9 * 4 * 8);
        cudaLaunchKernelEx(&c, conv_s1_kernel<2, 2, 8, false, true>,
            (const float*)cat0, w_out, (const float2*)coef0, (float*)d_out,
            (double2*)nullptr, 32, 128, 128, 128);
    }
}

// round 14
// speedup vs baseline: 1.0436x; 1.0436x over previous
#include <cuda_runtime.h>
#include <cstdint>
#include <math.h>

// ---------------------------------------------------------------------------
// UNet4LMCD round 13: R11 champion (PDL chain, LDS.128 weights, FFMA2) +
//  - tconv: single-chunk weight staging only (NO cl unroll — R12's regression)
//  - bn_finalize: trigger before sync (wider PDL overlap window)
// Inner loops otherwise byte-identical to the 1743us R11 kernel.
// ---------------------------------------------------------------------------

#define V0_ (128*128*128)
#define V1_ (64*64*64)
#define V2_ (32*32*32)
#define V3_ (16*16*16)
#define PMAX_ 2048

typedef unsigned long long ull;

__device__ float   g_s8  [64 * V3_];
__device__ float   g_cat2[64 * V2_];          // [tconv3 out (32) | s4 (32)]
__device__ float   g_cat1[48 * V1_];          // [tconv2 out (32) | s2 (16)]
__device__ float   g_cat0[32u * V0_];         // [tconv1 out (24) | s1 (8)]
__device__ double2 g_part[64 * PMAX_];
__device__ float2  g_coef0[32];
__device__ float2  g_coef1[48];
__device__ float2  g_coef2[64];
__device__ float2  g_coefs8[64];

// ---- PDL device helpers -----------------------------------------------------
__device__ __forceinline__ void pdl_sync()    { cudaGridDependencySynchronize(); }
__device__ __forceinline__ void pdl_trigger() { cudaTriggerProgrammaticLaunchCompletion(); }

// ---- packed f32x2 helpers --------------------------------------------------
__device__ __forceinline__ ull pack2(float lo, float hi) {
    ull r;
    asm("mov.b64 %0, {%1, %2};" : "=l"(r) : "f"(lo), "f"(hi));
    return r;
}
__device__ __forceinline__ ull fma2(ull a, ull b, ull c) {
    ull d;
    asm("fma.rn.f32x2 %0, %1, %2, %3;" : "=l"(d) : "l"(a), "l"(b), "l"(c));
    return d;
}
__device__ __forceinline__ float2 unpack2(ull v) {
    float2 f;
    asm("mov.b64 {%0, %1}, %2;" : "=f"(f.x), "=f"(f.y) : "l"(v));
    return f;
}
__device__ __forceinline__ ull ld64(const float2* p) {
    return *reinterpret_cast<const ull*>(p);
}
__device__ __forceinline__ void ld128(const float2* p, ull& a, ull& b) {
    const ulonglong2 v = *reinterpret_cast<const ulonglong2*>(p);
    a = v.x; b = v.y;
}
__device__ __forceinline__ float bnr(float v, float2 c) {
    return fmaxf(fmaf(v, c.x, c.y), 0.f);
}

// ---------------------------------------------------------------------------
// Fused BN-stats epilogue over flattened accumulators acc[CG][NT].
// ---------------------------------------------------------------------------
template <int CG, int NT>
__device__ __forceinline__ void stats_epilogue(const float (*acc)[NT],
                                               double2* __restrict__ part,
                                               int cb, int tid, int nthr) {
    float s[CG], q[CG];
#pragma unroll
    for (int g = 0; g < CG; g++) {
        float ss = 0.f, qq = 0.f;
#pragma unroll
        for (int t = 0; t < NT; t++) {
            ss += acc[g][t];
            qq = fmaf(acc[g][t], acc[g][t], qq);
        }
        s[g] = ss; q[g] = qq;
    }
#pragma unroll
    for (int o = 16; o > 0; o >>= 1) {
#pragma unroll
        for (int g = 0; g < CG; g++) {
            s[g] += __shfl_down_sync(0xffffffffu, s[g], o);
            q[g] += __shfl_down_sync(0xffffffffu, q[g], o);
        }
    }
    __shared__ float2 red[CG][8];
    const int wid = tid >> 5, lane = tid & 31;
    if (lane == 0) {
#pragma unroll
        for (int g = 0; g < CG; g++) red[g][wid] = make_float2(s[g], q[g]);
    }
    __syncthreads();
    const int nw = nthr >> 5;
    if (tid < CG) {
        double ds = 0.0, dq = 0.0;
        for (int w = 0; w < nw; w++) {
            ds += (double)red[tid][w].x;
            dq += (double)red[tid][w].y;
        }
        const int pidx = blockIdx.x + gridDim.x * blockIdx.y;
        part[(size_t)(cb + tid) * PMAX_ + pidx] = make_double2(ds, dq);
    }
}

// ---------------------------------------------------------------------------
// Stride-1 3x3x3 conv, packed: CG x TZ x TX(=8). Padded weight layout:
// 4 float2 per (g,ci,kd,kh) triplet -> (w0,w1) via LDS.128, w2 via LDS.64.
// ---------------------------------------------------------------------------
template <int CG, int TZ, int TX, bool STATS, bool APPLY>
__global__ void __launch_bounds__(128) conv_s1_kernel(
        const float* __restrict__ in, const float* __restrict__ wt,
        const float2* __restrict__ coef,
        float* __restrict__ out, double2* __restrict__ part,
        int Cin, int D, int H, int W) {
    static_assert(TX == 8, "conv_s1 needs TX==8");
    extern __shared__ __align__(16) float2 sw2[];
    const int cb   = blockIdx.z * CG;
    const int tid  = threadIdx.y * blockDim.x + threadIdx.x;
    const int nthr = blockDim.x * blockDim.y;
    for (int i = tid; i < CG * Cin * 27; i += nthr) {
        const float w = wt[(size_t)cb * Cin * 27 + i];
        const int tri = i / 3, t = i - tri * 3;
        sw2[tri * 4 + t] = make_float2(w, w);
    }
    __syncthreads();
    pdl_sync();                 // predecessor data (in, coef) needed below

    const int x0 = threadIdx.x * TX;
    const int y  = blockIdx.x * blockDim.y + threadIdx.y;
    const int z0 = blockIdx.y * TZ;

    ull accp[CG][TZ][TX / 2];
#pragma unroll
    for (int g = 0; g < CG; g++)
#pragma unroll
        for (int zz = 0; zz < TZ; zz++)
#pragma unroll
            for (int k = 0; k < TX / 2; k++) accp[g][zz][k] = 0ull;

    for (int ci = 0; ci < Cin; ci++) {
        const float* inc = in + (size_t)ci * D * H * W;
        float2 cf = APPLY ? coef[ci] : make_float2(1.f, 0.f);
#pragma unroll
        for (int pz = 0; pz < TZ + 2; pz++) {
            const int iz = z0 - 1 + pz;
            if (iz < 0 || iz >= D) continue;
#pragma unroll
            for (int kh = 0; kh < 3; kh++) {
                const int iy = y + kh - 1;
                if (iy < 0 || iy >= H) continue;
                const float* row = inc + ((size_t)iz * H + iy) * W;
                float r[TX + 2];
                const float4 v0 = *reinterpret_cast<const float4*>(row + x0);
                const float4 v1 = *reinterpret_cast<const float4*>(row + x0 + 4);
                if (APPLY) {
                    r[0] = (x0 > 0) ? bnr(row[x0 - 1], cf) : 0.f;
                    r[1] = bnr(v0.x, cf); r[2] = bnr(v0.y, cf);
                    r[3] = bnr(v0.z, cf); r[4] = bnr(v0.w, cf);
                    r[5] = bnr(v1.x, cf); r[6] = bnr(v1.y, cf);
                    r[7] = bnr(v1.z, cf); r[8] = bnr(v1.w, cf);
                    r[9] = (x0 + TX < W) ? bnr(row[x0 + TX], cf) : 0.f;
                } else {
                    r[0] = (x0 > 0) ? row[x0 - 1] : 0.f;
                    r[1] = v0.x; r[2] = v0.y; r[3] = v0.z; r[4] = v0.w;
                    r[5] = v1.x; r[6] = v1.y; r[7] = v1.z; r[8] = v1.w;
                    r[9] = (x0 + TX < W) ? row[x0 + TX] : 0.f;
                }
                // pair registers: E_k = (r[2k], r[2k+1]), O_k = (r[2k+1], r[2k+2])
                ull E[TX / 2 + 1], O[TX / 2];
#pragma unroll
                for (int k = 0; k <= TX / 2; k++) E[k] = pack2(r[2 * k], r[2 * k + 1]);
#pragma unroll
                for (int k = 0; k < TX / 2; k++)  O[k] = pack2(r[2 * k + 1], r[2 * k + 2]);
#pragma unroll
                for (int zz = 0; zz < TZ; zz++) {
                    const int kd = iz - (z0 + zz) + 1;
                    if (kd < 0 || kd > 2) continue;
#pragma unroll
                    for (int g = 0; g < CG; g++) {
                        const float2* wp = sw2 +
                            (((size_t)g * Cin + ci) * 9 + kd * 3 + kh) * 4;
                        ull w0, w1; ld128(wp, w0, w1);
                        const ull w2 = ld64(wp + 2);
#pragma unroll
                        for (int k = 0; k < TX / 2; k++)
                            accp[g][zz][k] = fma2(E[k], w0,
                                             fma2(O[k], w1,
                                             fma2(E[k + 1], w2, accp[g][zz][k])));
                    }
                }
            }
        }
    }
    pdl_trigger();              // successor may launch; epilogue remains

#pragma unroll
    for (int g = 0; g < CG; g++)
#pragma unroll
        for (int zz = 0; zz < TZ; zz++) {
            float* orow = out + (((size_t)(cb + g) * D + z0 + zz) * H + y) * W + x0;
#pragma unroll
            for (int k = 0; k < TX / 2; k += 2) {
                const float2 a = unpack2(accp[g][zz][k]);
                const float2 b = unpack2(accp[g][zz][k + 1]);
                *reinterpret_cast<float4*>(orow + 2 * k) = make_float4(a.x, a.y, b.x, b.y);
            }
        }
    if (STATS) {
        float acc_f[CG][TZ * TX];
#pragma unroll
        for (int g = 0; g < CG; g++)
#pragma unroll
            for (int zz = 0; zz < TZ; zz++)
#pragma unroll
                for (int k = 0; k < TX / 2; k++) {
                    const float2 a = unpack2(accp[g][zz][k]);
                    acc_f[g][zz * TX + 2 * k]     = a.x;
                    acc_f[g][zz * TX + 2 * k + 1] = a.y;
                }
        stats_epilogue<CG, TZ * TX>(acc_f, part, cb, tid, nthr);
    }
}

// ---------------------------------------------------------------------------
// Stride-2 3x3x3 conv, packed: CG x TX (2 or 4). Padded weight layout.
// ---------------------------------------------------------------------------
template <int CG, int TX, bool STATS>
__global__ void conv_s2_kernel(
        const float* __restrict__ in, const float* __restrict__ wt,
        const float2* __restrict__ coef,
        float* __restrict__ out, double2* __restrict__ part,
        int Cin, int Di, int Hi, int Wi, int Do, int Ho, int Wo) {
    static_assert(TX == 2 || TX == 4, "conv_s2 needs TX in {2,4}");
    extern __shared__ __align__(16) float2 sw2[];
    const int cb   = blockIdx.z * CG;
    const int tid  = threadIdx.y * blockDim.x + threadIdx.x;
    const int nthr = blockDim.x * blockDim.y;
    for (int i = tid; i < CG * Cin * 27; i += nthr) {
        const float w = wt[(size_t)cb * Cin * 27 + i];
        const int tri = i / 3, t = i - tri * 3;
        sw2[tri * 4 + t] = make_float2(w, w);
    }
    __syncthreads();
    pdl_sync();

    const int x0 = threadIdx.x * TX;
    const int bx = 2 * x0;
    const int y  = blockIdx.x * blockDim.y + threadIdx.y;
    const int z  = blockIdx.y;

    ull accp[CG][TX / 2];
#pragma unroll
    for (int g = 0; g < CG; g++)
#pragma unroll
        for (int k = 0; k < TX / 2; k++) accp[g][k] = 0ull;

    for (int ci = 0; ci < Cin; ci++) {
        const float* inc = in + (size_t)ci * Di * Hi * Wi;
        const float2 cf = coef[ci];
#pragma unroll
        for (int kd = 0; kd < 3; kd++) {
            const int iz = 2 * z + kd - 1;
            if (iz < 0 || iz >= Di) continue;
#pragma unroll
            for (int kh = 0; kh < 3; kh++) {
                const int iy = 2 * y + kh - 1;
                if (iy < 0 || iy >= Hi) continue;
                const float* row = inc + ((size_t)iz * Hi + iy) * Wi;
                float rr[2 * TX + 2];
                rr[0] = (bx > 0) ? bnr(row[bx - 1], cf) : 0.f;
#pragma unroll
                for (int q = 0; q < TX / 2; q++) {
                    const float4 v = *reinterpret_cast<const float4*>(row + bx + 4 * q);
                    rr[4 * q + 1] = bnr(v.x, cf); rr[4 * q + 2] = bnr(v.y, cf);
                    rr[4 * q + 3] = bnr(v.z, cf); rr[4 * q + 4] = bnr(v.w, cf);
                }
                rr[2 * TX + 1] = (bx + 2 * TX < Wi) ? bnr(row[bx + 2 * TX], cf) : 0.f;
                ull M[3][TX / 2];
#pragma unroll
                for (int j = 0; j < 3; j++)
#pragma unroll
                    for (int k = 0; k < TX / 2; k++)
                        M[j][k] = pack2(rr[4 * k + j], rr[4 * k + j + 2]);
#pragma unroll
                for (int g = 0; g < CG; g++) {
                    const float2* wp = sw2 +
                        (((size_t)g * Cin + ci) * 9 + kd * 3 + kh) * 4;
                    ull w0, w1; ld128(wp, w0, w1);
                    const ull w2 = ld64(wp + 2);
#pragma unroll
                    for (int k = 0; k < TX / 2; k++)
                        accp[g][k] = fma2(M[0][k], w0,
                                     fma2(M[1][k], w1,
                                     fma2(M[2][k], w2, accp[g][k])));
                }
            }
        }
    }
    pdl_trigger();

#pragma unroll
    for (int g = 0; g < CG; g++) {
        float* orow = out + (((size_t)(cb + g) * Do + z) * Ho + y) * Wo + x0;
        if constexpr (TX == 2) {
            *reinterpret_cast<float2*>(orow) = unpack2(accp[g][0]);
        } else {
            const float2 a = unpack2(accp[g][0]);
            const float2 b = unpack2(accp[g][1]);
            *reinterpret_cast<float4*>(orow) = make_float4(a.x, a.y, b.x, b.y);
        }
    }
    if (STATS) {
        float acc_f[CG][TX];
#pragma unroll
        for (int g = 0; g < CG; g++)
#pragma unroll
            for (int k = 0; k < TX / 2; k++) {
                const float2 a = unpack2(accp[g][k]);
                acc_f[g][2 * k] = a.x; acc_f[g][2 * k + 1] = a.y;
            }
        stats_epilogue<CG, TX>(acc_f, part, cb, tid, nthr);
    }
}

// ---------------------------------------------------------------------------
// Stride-2 transposed conv, packed y-pair tile, TX in {4,8}.
// Single-chunk weight staging (Cin <= 64 in smem); inner loop identical to
// R11 (NO cl unroll).
// ---------------------------------------------------------------------------
template <int CG, int TX, bool STATS>
__global__ void tconv_kernel(
        const float* __restrict__ in, const float* __restrict__ wt,
        const float2* __restrict__ coef,
        float* __restrict__ out, double2* __restrict__ part,
        int Cin, int Di, int Hi, int Wi) {
    static_assert(TX == 4 || TX == 8, "tconv needs TX in {4,8}");
    const int Do = 2 * Di, Ho = 2 * Hi, Wo = 2 * Wi;
    extern __shared__ __align__(16) float2 sw2[];
    const int cb   = blockIdx.z * CG;
    const int tid  = threadIdx.y * blockDim.x + threadIdx.x;
    const int nthr = blockDim.x * blockDim.y;

    const int x0 = threadIdx.x * TX;
    const int i0 = x0 >> 1;
    const int yp = blockIdx.x * blockDim.y + threadIdx.y;
    const int z  = blockIdx.y;

    ull accpE[CG][TX / 2], accpO[CG][TX / 2];
#pragma unroll
    for (int g = 0; g < CG; g++)
#pragma unroll
        for (int k = 0; k < TX / 2; k++) { accpE[g][k] = 0ull; accpO[g][k] = 0ull; }

    const bool hb = (yp + 1 < Hi);
    const bool xe = (i0 + TX / 2 < Wi);

    // single-chunk staging: 6 float2 per (g, cl, kd)
    for (int i = tid; i < CG * Cin * 3; i += nthr) {
        const int g   = i / (Cin * 3);
        const int rem = i - g * (Cin * 3);
        const int cl  = rem / 3;
        const int kd  = rem - cl * 3;
        const float* w = wt + ((size_t)(cb + g) * Cin + cl) * 27 + kd * 9;
        float2* p = sw2 + (size_t)i * 6;
        p[0] = make_float2(w[4], w[3]);   // (wa1, wa0)  kh=1
        p[1] = make_float2(0.f,  w[5]);   // (0,   wa2)
        p[2] = make_float2(w[1], w[0]);   // (wb1, wb0)  kh=0
        p[3] = make_float2(w[7], w[6]);   // (wc1, wc0)  kh=2
        p[4] = make_float2(0.f,  w[2]);   // (0,   wb2)
        p[5] = make_float2(0.f,  w[8]);   // (0,   wc2)
    }
    __syncthreads();
    pdl_sync();

    for (int cl = 0; cl < Cin; cl++) {
        const float* inc = in + (size_t)cl * Di * Hi * Wi;
        const float2 cf = coef[cl];
#pragma unroll
        for (int kd = 0; kd < 3; kd++) {
            const int dz = z - 1 + kd;
            if (dz < 0 || (dz & 1)) continue;
            const int iz = dz >> 1;
            if (iz >= Di) continue;

            const float* prow = inc + ((size_t)iz * Hi + yp) * Wi;
            float r[TX / 2 + 1], s[TX / 2 + 1];
            if constexpr (TX == 8) {
                const float4 v = *reinterpret_cast<const float4*>(prow + i0);
                r[0] = bnr(v.x, cf); r[1] = bnr(v.y, cf);
                r[2] = bnr(v.z, cf); r[3] = bnr(v.w, cf);
                r[4] = xe ? bnr(prow[i0 + 4], cf) : 0.f;
            } else {
                const float2 v = *reinterpret_cast<const float2*>(prow + i0);
                r[0] = bnr(v.x, cf); r[1] = bnr(v.y, cf);
                r[2] = xe ? bnr(prow[i0 + 2], cf) : 0.f;
            }
            if (hb) {
                const float* qrow = prow + Wi;
                if constexpr (TX == 8) {
                    const float4 u = *reinterpret_cast<const float4*>(qrow + i0);
                    s[0] = bnr(u.x, cf); s[1] = bnr(u.y, cf);
                    s[2] = bnr(u.z, cf); s[3] = bnr(u.w, cf);
                    s[4] = xe ? bnr(qrow[i0 + 4], cf) : 0.f;
                } else {
                    const float2 u = *reinterpret_cast<const float2*>(qrow + i0);
                    s[0] = bnr(u.x, cf); s[1] = bnr(u.y, cf);
                    s[2] = xe ? bnr(qrow[i0 + 2], cf) : 0.f;
                }
            } else {
#pragma unroll
                for (int e = 0; e <= TX / 2; e++) s[e] = 0.f;
            }
            ull rb[TX / 2 + 1], sb[TX / 2 + 1];
#pragma unroll
            for (int e = 0; e <= TX / 2; e++) {
                rb[e] = pack2(r[e], r[e]);
                sb[e] = pack2(s[e], s[e]);
            }
#pragma unroll
            for (int g = 0; g < CG; g++) {
                const float2* p = sw2 + ((size_t)(g * Cin + cl) * 3 + kd) * 6;
                ull p0, p1; ld128(p,     p0, p1);
                ull p2, p3; ld128(p + 2, p2, p3);
                ull p4, p5; ld128(p + 4, p4, p5);
#pragma unroll
                for (int e = 0; e < TX / 2; e++) {
                    accpE[g][e] = fma2(rb[e], p0, fma2(rb[e + 1], p1, accpE[g][e]));
                    accpO[g][e] = fma2(rb[e], p2,
                                  fma2(sb[e], p3,
                                  fma2(rb[e + 1], p4,
                                  fma2(sb[e + 1], p5, accpO[g][e]))));
                }
            }
        }
    }
    pdl_trigger();

#pragma unroll
    for (int g = 0; g < CG; g++) {
        float* erow = out + (((size_t)(cb + g) * Do + z) * Ho + 2 * yp) * Wo + x0;
        float* orow = erow + Wo;
#pragma unroll
        for (int k = 0; k < TX / 2; k += 2) {
            const float2 a = unpack2(accpE[g][k]);
            const float2 b = unpack2(accpE[g][k + 1]);
            *reinterpret_cast<float4*>(erow + 2 * k) = make_float4(a.x, a.y, b.x, b.y);
            const float2 c = unpack2(accpO[g][k]);
            const float2 d = unpack2(accpO[g][k + 1]);
            *reinterpret_cast<float4*>(orow + 2 * k) = make_float4(c.x, c.y, d.x, d.y);
        }
    }
    if (STATS) {
        float acc_f[CG][2 * TX];
#pragma unroll
        for (int g = 0; g < CG; g++)
#pragma unroll
            for (int k = 0; k < TX / 2; k++) {
                const float2 a = unpack2(accpE[g][k]);
                const float2 b = unpack2(accpO[g][k]);
                acc_f[g][2 * k]          = a.x;
                acc_f[g][2 * k + 1]      = a.y;
                acc_f[g][TX + 2 * k]     = b.x;
                acc_f[g][TX + 2 * k + 1] = b.y;
            }
        stats_epilogue<CG, 2 * TX>(acc_f, part, cb, tid, nthr);
    }
}

// ---------------------------------------------------------------------------
// BN finalize: partials -> per-channel (a, b) coefficients.
// Triggers BEFORE sync: successor launch/prologue overlaps maximally; its own
// pdl_sync still guarantees it sees this kernel's results.
// ---------------------------------------------------------------------------
__global__ void bn_finalize(const double2* __restrict__ part,
                            float2* __restrict__ coef,
                            const float* __restrict__ gam,
                            const float* __restrict__ bet,
                            int P, int V, float eps) {
    pdl_trigger();
    pdl_sync();
    const int c = blockIdx.x;
    double s = 0.0, q = 0.0;
    for (int i = threadIdx.x; i < P; i += 256) {
        const double2 pp = part[(size_t)c * PMAX_ + i];
        s += pp.x; q += pp.y;
    }
    __shared__ double ss[256], sq[256];
    ss[threadIdx.x] = s; sq[threadIdx.x] = q;
    __syncthreads();
    for (int o = 128; o > 0; o >>= 1) {
        if (threadIdx.x < o) {
            ss[threadIdx.x] += ss[threadIdx.x + o];
            sq[threadIdx.x] += sq[threadIdx.x + o];
        }
        __syncthreads();
    }
    if (threadIdx.x == 0) {
        const double mean = ss[0] / V;
        const double var  = sq[0] / V - mean * mean;
        const float inv_std = (float)(1.0 / sqrt(var + (double)eps));
        const float a = inv_std * gam[c];
        const float b = fmaf(-(float)mean, a, bet[c]);
        coef[c] = make_float2(a, b);
    }
}

// ---------------------------------------------------------------------------
// Host orchestration — all launches via cudaLaunchKernelEx with PDL.
// ---------------------------------------------------------------------------
extern "C" void kernel_launch(void* const* d_in, const int* in_sizes, int n_in,
                              void* d_out, int out_size) {
    (void)in_sizes; (void)n_in; (void)out_size;

    const float* x     = (const float*)d_in[0];
    const float* w0    = (const float*)d_in[1];
    const float* g0    = (const float*)d_in[2];
    const float* b0    = (const float*)d_in[3];
    const float* w1    = (const float*)d_in[4];
    const float* g1    = (const float*)d_in[5];
    const float* b1    = (const float*)d_in[6];
    const float* w2    = (const float*)d_in[7];
    const float* g2    = (const float*)d_in[8];
    const float* b2    = (const float*)d_in[9];
    const float* w3    = (const float*)d_in[10];
    const float* g3    = (const float*)d_in[11];
    const float* b3    = (const float*)d_in[12];
    const float* wt3   = (const float*)d_in[13];
    const float* gt3   = (const float*)d_in[14];
    const float* bt3   = (const float*)d_in[15];
    const float* wt2   = (const float*)d_in[16];
    const float* gt2   = (const float*)d_in[17];
    const float* bt2   = (const float*)d_in[18];
    const float* wt1   = (const float*)d_in[19];
    const float* gt1   = (const float*)d_in[20];
    const float* bt1   = (const float*)d_in[21];
    const float* w_out = (const float*)d_in[22];

    float *cat0, *cat1, *cat2, *s8;
    double2* part;
    float2 *coef0, *coef1, *coef2, *coefs8;
    cudaGetSymbolAddress((void**)&cat0,   g_cat0);
    cudaGetSymbolAddress((void**)&cat1,   g_cat1);
    cudaGetSymbolAddress((void**)&cat2,   g_cat2);
    cudaGetSymbolAddress((void**)&s8,     g_s8);
    cudaGetSymbolAddress((void**)&part,   g_part);
    cudaGetSymbolAddress((void**)&coef0,  g_coef0);
    cudaGetSymbolAddress((void**)&coef1,  g_coef1);
    cudaGetSymbolAddress((void**)&coef2,  g_coef2);
    cudaGetSymbolAddress((void**)&coefs8, g_coefs8);

    float* s1 = cat0 + (size_t)24 * V0_;
    float* s2 = cat1 + (size_t)32 * V1_;
    float* s4 = cat2 + (size_t)32 * V2_;

    cudaLaunchAttribute pdl_attr[1];
    pdl_attr[0].id = cudaLaunchAttributeProgrammaticStreamSerialization;
    pdl_attr[0].val.programmaticStreamSerializationAllowed = 1;

    auto cfg = [&](dim3 g, dim3 b, size_t smem) {
        cudaLaunchConfig_t c = {};
        c.gridDim = g; c.blockDim = b; c.dynamicSmemBytes = smem;
        c.stream = 0; c.attrs = pdl_attr; c.numAttrs = 1;
        return c;
    };

    // ---- encoder ----
    // conv0: 8->8, 128^3, stride 1 (raw input)
    {
        cudaLaunchConfig_t c = cfg(dim3(16, 128, 1), dim3(16, 8), 8 * 8 * 9 * 4 * 8);
        cudaLaunchKernelEx(&c, conv_s1_kernel<8, 1, 8, true, false>,
            x, w0, (const float2*)nullptr, s1, part, 8, 128, 128, 128);
    }
    {
        cudaLaunchConfig_t c = cfg(dim3(8, 1, 1), dim3(256, 1, 1), 0);
        cudaLaunchKernelEx(&c, bn_finalize,
            (const double2*)part, coef0 + 24, g0, b0, 16 * 128, V0_, 1e-5f);
    }

    // conv1: 8->16, stride 2 -> 64^3
    {
        cudaLaunchConfig_t c = cfg(dim3(8, 64, 2), dim3(16, 8), 8 * 8 * 9 * 4 * 8);
        cudaLaunchKernelEx(&c, conv_s2_kernel<8, 4, true>,
            (const float*)s1, w1, (const float2*)(coef0 + 24), s2, part,
            8, 128, 128, 128, 64, 64, 64);
    }
    {
        cudaLaunchConfig_t c = cfg(dim3(16, 1, 1), dim3(256, 1, 1), 0);
        cudaLaunchKernelEx(&c, bn_finalize,
            (const double2*)part, coef1 + 32, g1, b1, 8 * 64, V1_, 1e-5f);
    }

    // conv2: 16->32, stride 2 -> 32^3 (CG=4)
    {
        cudaLaunchConfig_t c = cfg(dim3(4, 32, 8), dim3(8, 8), 4 * 16 * 9 * 4 * 8);
        cudaLaunchKernelEx(&c, conv_s2_kernel<4, 4, true>,
            (const float*)s2, w2, (const float2*)(coef1 + 32), s4, part,
            16, 64, 64, 64, 32, 32, 32);
    }
    {
        cudaLaunchConfig_t c = cfg(dim3(32, 1, 1), dim3(256, 1, 1), 0);
        cudaLaunchKernelEx(&c, bn_finalize,
            (const double2*)part, coef2 + 32, g2, b2, 4 * 32, V2_, 1e-5f);
    }

    // conv3: 32->64, stride 2 -> 16^3 (CG=2, TX=2)
    {
        cudaLaunchConfig_t c = cfg(dim3(1, 16, 32), dim3(8, 16), 2 * 32 * 9 * 4 * 8);
        cudaLaunchKernelEx(&c, conv_s2_kernel<2, 2, true>,
            (const float*)s4, w3, (const float2*)(coef2 + 32), s8, part,
            32, 32, 32, 32, 16, 16, 16);
    }
    {
        cudaLaunchConfig_t c = cfg(dim3(64, 1, 1), dim3(256, 1, 1), 0);
        cudaLaunchKernelEx(&c, bn_finalize,
            (const double2*)part, coefs8, g3, b3, 1 * 16, V3_, 1e-5f);
    }

    // ---- decoder ----  (tconv smem: CG*Cin*3*6 float2)
    // tconv3: 64->32, 16^3 -> 32^3 (CG=2, TX=4)
    {
        cudaLaunchConfig_t c = cfg(dim3(2, 32, 16), dim3(8, 8), 2 * 64 * 3 * 6 * 8);
        cudaLaunchKernelEx(&c, tconv_kernel<2, 4, true>,
            (const float*)s8, wt3, (const float2*)coefs8, cat2, part,
            64, 16, 16, 16);
    }
    {
        cudaLaunchConfig_t c = cfg(dim3(32, 1, 1), dim3(256, 1, 1), 0);
        cudaLaunchKernelEx(&c, bn_finalize,
            (const double2*)part, coef2, gt3, bt3, 2 * 32, V2_, 1e-5f);
    }

    // tconv2: 64->32, 32^3 -> 64^3
    {
        cudaLaunchConfig_t c = cfg(dim3(2, 64, 8), dim3(8, 16), 4 * 64 * 3 * 6 * 8);
        cudaLaunchKernelEx(&c, tconv_kernel<4, 8, true>,
            (const float*)cat2, wt2, (const float2*)coef2, cat1, part,
            64, 32, 32, 32);
    }
    {
        cudaLaunchConfig_t c = cfg(dim3(32, 1, 1), dim3(256, 1, 1), 0);
        cudaLaunchKernelEx(&c, bn_finalize,
            (const double2*)part, coef1, gt2, bt2, 2 * 64, V1_, 1e-5f);
    }

    // tconv1: 48->24, 64^3 -> 128^3
    {
        cudaLaunchConfig_t c = cfg(dim3(8, 128, 6), dim3(16, 8), 4 * 48 * 3 * 6 * 8);
        cudaLaunchKernelEx(&c, tconv_kernel<4, 8, true>,
            (const float*)cat1, wt1, (const float2*)coef1, cat0, part,
            48, 64, 64, 64);
    }
    {
        cudaLaunchConfig_t c = cfg(dim3(24, 1, 1), dim3(256, 1, 1), 0);
        cudaLaunchKernelEx(&c, bn_finalize,
            (const double2*)part, coef0, gt1, bt1, 8 * 128, V0_, 1e-5f);
    }

    // conv_out: 32->2, 128^3, stride 1, TZ=2, folded BN on cat0 loads
    {
        cudaLaunchConfig_t c = cfg(dim3(16, 64, 1), dim3(16, 8), 2 * 32 * 9 * 4 * 8);
        cudaLaunchKernelEx(&c, conv_s1_kernel<2, 2, 8, false, true>,
            (const float*)cat0, w_out, (const float2*)coef0, (float*)d_out,
            (double2*)nullptr, 32, 128, 128, 128);
    }
}

// round 15
// speedup vs baseline: 1.1578x; 1.1094x over previous
#include <cuda_runtime.h>
#include <cstdint>
#include <math.h>

// ---------------------------------------------------------------------------
// UNet4LMCD round 14: exact restore of the R11 champion (1743us).
// PDL chain + LDS.128 weights + FFMA2 + chunked tconv staging.
// ---------------------------------------------------------------------------

#define V0_ (128*128*128)
#define V1_ (64*64*64)
#define V2_ (32*32*32)
#define V3_ (16*16*16)
#define PMAX_ 2048

typedef unsigned long long ull;

__device__ float   g_s8  [64 * V3_];
__device__ float   g_cat2[64 * V2_];          // [tconv3 out (32) | s4 (32)]
__device__ float   g_cat1[48 * V1_];          // [tconv2 out (32) | s2 (16)]
__device__ float   g_cat0[32u * V0_];         // [tconv1 out (24) | s1 (8)]
__device__ double2 g_part[64 * PMAX_];
__device__ float2  g_coef0[32];
__device__ float2  g_coef1[48];
__device__ float2  g_coef2[64];
__device__ float2  g_coefs8[64];

// ---- PDL device helpers -----------------------------------------------------
__device__ __forceinline__ void pdl_sync()    { cudaGridDependencySynchronize(); }
__device__ __forceinline__ void pdl_trigger() { cudaTriggerProgrammaticLaunchCompletion(); }

// ---- packed f32x2 helpers --------------------------------------------------
__device__ __forceinline__ ull pack2(float lo, float hi) {
    ull r;
    asm("mov.b64 %0, {%1, %2};" : "=l"(r) : "f"(lo), "f"(hi));
    return r;
}
__device__ __forceinline__ ull fma2(ull a, ull b, ull c) {
    ull d;
    asm("fma.rn.f32x2 %0, %1, %2, %3;" : "=l"(d) : "l"(a), "l"(b), "l"(c));
    return d;
}
__device__ __forceinline__ float2 unpack2(ull v) {
    float2 f;
    asm("mov.b64 {%0, %1}, %2;" : "=f"(f.x), "=f"(f.y) : "l"(v));
    return f;
}
__device__ __forceinline__ ull ld64(const float2* p) {
    return *reinterpret_cast<const ull*>(p);
}
__device__ __forceinline__ void ld128(const float2* p, ull& a, ull& b) {
    const ulonglong2 v = *reinterpret_cast<const ulonglong2*>(p);
    a = v.x; b = v.y;
}
__device__ __forceinline__ float bnr(float v, float2 c) {
    return fmaxf(fmaf(v, c.x, c.y), 0.f);
}

// ---------------------------------------------------------------------------
// Fused BN-stats epilogue over flattened accumulators acc[CG][NT].
// ---------------------------------------------------------------------------
template <int CG, int NT>
__device__ __forceinline__ void stats_epilogue(const float (*acc)[NT],
                                               double2* __restrict__ part,
                                               int cb, int tid, int nthr) {
    float s[CG], q[CG];
#pragma unroll
    for (int g = 0; g < CG; g++) {
        float ss = 0.f, qq = 0.f;
#pragma unroll
        for (int t = 0; t < NT; t++) {
            ss += acc[g][t];
            qq = fmaf(acc[g][t], acc[g][t], qq);
        }
        s[g] = ss; q[g] = qq;
    }
#pragma unroll
    for (int o = 16; o > 0; o >>= 1) {
#pragma unroll
        for (int g = 0; g < CG; g++) {
            s[g] += __shfl_down_sync(0xffffffffu, s[g], o);
            q[g] += __shfl_down_sync(0xffffffffu, q[g], o);
        }
    }
    __shared__ float2 red[CG][8];
    const int wid = tid >> 5, lane = tid & 31;
    if (lane == 0) {
#pragma unroll
        for (int g = 0; g < CG; g++) red[g][wid] = make_float2(s[g], q[g]);
    }
    __syncthreads();
    const int nw = nthr >> 5;
    if (tid < CG) {
        double ds = 0.0, dq = 0.0;
        for (int w = 0; w < nw; w++) {
            ds += (double)red[tid][w].x;
            dq += (double)red[tid][w].y;
        }
        const int pidx = blockIdx.x + gridDim.x * blockIdx.y;
        part[(size_t)(cb + tid) * PMAX_ + pidx] = make_double2(ds, dq);
    }
}

// ---------------------------------------------------------------------------
// Stride-1 3x3x3 conv, packed: CG x TZ x TX(=8). Padded weight layout:
// 4 float2 per (g,ci,kd,kh) triplet -> (w0,w1) via LDS.128, w2 via LDS.64.
// ---------------------------------------------------------------------------
template <int CG, int TZ, int TX, bool STATS, bool APPLY>
__global__ void __launch_bounds__(128) conv_s1_kernel(
        const float* __restrict__ in, const float* __restrict__ wt,
        const float2* __restrict__ coef,
        float* __restrict__ out, double2* __restrict__ part,
        int Cin, int D, int H, int W) {
    static_assert(TX == 8, "conv_s1 needs TX==8");
    extern __shared__ __align__(16) float2 sw2[];
    const int cb   = blockIdx.z * CG;
    const int tid  = threadIdx.y * blockDim.x + threadIdx.x;
    const int nthr = blockDim.x * blockDim.y;
    for (int i = tid; i < CG * Cin * 27; i += nthr) {
        const float w = wt[(size_t)cb * Cin * 27 + i];
        const int tri = i / 3, t = i - tri * 3;
        sw2[tri * 4 + t] = make_float2(w, w);
    }
    __syncthreads();
    pdl_sync();                 // predecessor data (in, coef) needed below

    const int x0 = threadIdx.x * TX;
    const int y  = blockIdx.x * blockDim.y + threadIdx.y;
    const int z0 = blockIdx.y * TZ;

    ull accp[CG][TZ][TX / 2];
#pragma unroll
    for (int g = 0; g < CG; g++)
#pragma unroll
        for (int zz = 0; zz < TZ; zz++)
#pragma unroll
            for (int k = 0; k < TX / 2; k++) accp[g][zz][k] = 0ull;

    for (int ci = 0; ci < Cin; ci++) {
        const float* inc = in + (size_t)ci * D * H * W;
        float2 cf = APPLY ? coef[ci] : make_float2(1.f, 0.f);
#pragma unroll
        for (int pz = 0; pz < TZ + 2; pz++) {
            const int iz = z0 - 1 + pz;
            if (iz < 0 || iz >= D) continue;
#pragma unroll
            for (int kh = 0; kh < 3; kh++) {
                const int iy = y + kh - 1;
                if (iy < 0 || iy >= H) continue;
                const float* row = inc + ((size_t)iz * H + iy) * W;
                float r[TX + 2];
                const float4 v0 = *reinterpret_cast<const float4*>(row + x0);
                const float4 v1 = *reinterpret_cast<const float4*>(row + x0 + 4);
                if (APPLY) {
                    r[0] = (x0 > 0) ? bnr(row[x0 - 1], cf) : 0.f;
                    r[1] = bnr(v0.x, cf); r[2] = bnr(v0.y, cf);
                    r[3] = bnr(v0.z, cf); r[4] = bnr(v0.w, cf);
                    r[5] = bnr(v1.x, cf); r[6] = bnr(v1.y, cf);
                    r[7] = bnr(v1.z, cf); r[8] = bnr(v1.w, cf);
                    r[9] = (x0 + TX < W) ? bnr(row[x0 + TX], cf) : 0.f;
                } else {
                    r[0] = (x0 > 0) ? row[x0 - 1] : 0.f;
                    r[1] = v0.x; r[2] = v0.y; r[3] = v0.z; r[4] = v0.w;
                    r[5] = v1.x; r[6] = v1.y; r[7] = v1.z; r[8] = v1.w;
                    r[9] = (x0 + TX < W) ? row[x0 + TX] : 0.f;
                }
                // pair registers: E_k = (r[2k], r[2k+1]), O_k = (r[2k+1], r[2k+2])
                ull E[TX / 2 + 1], O[TX / 2];
#pragma unroll
                for (int k = 0; k <= TX / 2; k++) E[k] = pack2(r[2 * k], r[2 * k + 1]);
#pragma unroll
                for (int k = 0; k < TX / 2; k++)  O[k] = pack2(r[2 * k + 1], r[2 * k + 2]);
#pragma unroll
                for (int zz = 0; zz < TZ; zz++) {
                    const int kd = iz - (z0 + zz) + 1;
                    if (kd < 0 || kd > 2) continue;
#pragma unroll
                    for (int g = 0; g < CG; g++) {
                        const float2* wp = sw2 +
                            (((size_t)g * Cin + ci) * 9 + kd * 3 + kh) * 4;
                        ull w0, w1; ld128(wp, w0, w1);
                        const ull w2 = ld64(wp + 2);
#pragma unroll
                        for (int k = 0; k < TX / 2; k++)
                            accp[g][zz][k] = fma2(E[k], w0,
                                             fma2(O[k], w1,
                                             fma2(E[k + 1], w2, accp[g][zz][k])));
                    }
                }
            }
        }
    }
    pdl_trigger();              // successor may launch; epilogue remains

#pragma unroll
    for (int g = 0; g < CG; g++)
#pragma unroll
        for (int zz = 0; zz < TZ; zz++) {
            float* orow = out + (((size_t)(cb + g) * D + z0 + zz) * H + y) * W + x0;
#pragma unroll
            for (int k = 0; k < TX / 2; k += 2) {
                const float2 a = unpack2(accp[g][zz][k]);
                const float2 b = unpack2(accp[g][zz][k + 1]);
                *reinterpret_cast<float4*>(orow + 2 * k) = make_float4(a.x, a.y, b.x, b.y);
            }
        }
    if (STATS) {
        float acc_f[CG][TZ * TX];
#pragma unroll
        for (int g = 0; g < CG; g++)
#pragma unroll
            for (int zz = 0; zz < TZ; zz++)
#pragma unroll
                for (int k = 0; k < TX / 2; k++) {
                    const float2 a = unpack2(accp[g][zz][k]);
                    acc_f[g][zz * TX + 2 * k]     = a.x;
                    acc_f[g][zz * TX + 2 * k + 1] = a.y;
                }
        stats_epilogue<CG, TZ * TX>(acc_f, part, cb, tid, nthr);
    }
}

// ---------------------------------------------------------------------------
// Stride-2 3x3x3 conv, packed: CG x TX (2 or 4). Padded weight layout.
// ---------------------------------------------------------------------------
template <int CG, int TX, bool STATS>
__global__ void conv_s2_kernel(
        const float* __restrict__ in, const float* __restrict__ wt,
        const float2* __restrict__ coef,
        float* __restrict__ out, double2* __restrict__ part,
        int Cin, int Di, int Hi, int Wi, int Do, int Ho, int Wo) {
    static_assert(TX == 2 || TX == 4, "conv_s2 needs TX in {2,4}");
    extern __shared__ __align__(16) float2 sw2[];
    const int cb   = blockIdx.z * CG;
    const int tid  = threadIdx.y * blockDim.x + threadIdx.x;
    const int nthr = blockDim.x * blockDim.y;
    for (int i = tid; i < CG * Cin * 27; i += nthr) {
        const float w = wt[(size_t)cb * Cin * 27 + i];
        const int tri = i / 3, t = i - tri * 3;
        sw2[tri * 4 + t] = make_float2(w, w);
    }
    __syncthreads();
    pdl_sync();

    const int x0 = threadIdx.x * TX;
    const int bx = 2 * x0;
    const int y  = blockIdx.x * blockDim.y + threadIdx.y;
    const int z  = blockIdx.y;

    ull accp[CG][TX / 2];
#pragma unroll
    for (int g = 0; g < CG; g++)
#pragma unroll
        for (int k = 0; k < TX / 2; k++) accp[g][k] = 0ull;

    for (int ci = 0; ci < Cin; ci++) {
        const float* inc = in + (size_t)ci * Di * Hi * Wi;
        const float2 cf = coef[ci];
#pragma unroll
        for (int kd = 0; kd < 3; kd++) {
            const int iz = 2 * z + kd - 1;
            if (iz < 0 || iz >= Di) continue;
#pragma unroll
            for (int kh = 0; kh < 3; kh++) {
                const int iy = 2 * y + kh - 1;
                if (iy < 0 || iy >= Hi) continue;
                const float* row = inc + ((size_t)iz * Hi + iy) * Wi;
                float rr[2 * TX + 2];
                rr[0] = (bx > 0) ? bnr(row[bx - 1], cf) : 0.f;
#pragma unroll
                for (int q = 0; q < TX / 2; q++) {
                    const float4 v = *reinterpret_cast<const float4*>(row + bx + 4 * q);
                    rr[4 * q + 1] = bnr(v.x, cf); rr[4 * q + 2] = bnr(v.y, cf);
                    rr[4 * q + 3] = bnr(v.z, cf); rr[4 * q + 4] = bnr(v.w, cf);
                }
                rr[2 * TX + 1] = (bx + 2 * TX < Wi) ? bnr(row[bx + 2 * TX], cf) : 0.f;
                ull M[3][TX / 2];
#pragma unroll
                for (int j = 0; j < 3; j++)
#pragma unroll
                    for (int k = 0; k < TX / 2; k++)
                        M[j][k] = pack2(rr[4 * k + j], rr[4 * k + j + 2]);
#pragma unroll
                for (int g = 0; g < CG; g++) {
                    const float2* wp = sw2 +
                        (((size_t)g * Cin + ci) * 9 + kd * 3 + kh) * 4;
                    ull w0, w1; ld128(wp, w0, w1);
                    const ull w2 = ld64(wp + 2);
#pragma unroll
                    for (int k = 0; k < TX / 2; k++)
                        accp[g][k] = fma2(M[0][k], w0,
                                     fma2(M[1][k], w1,
                                     fma2(M[2][k], w2, accp[g][k])));
                }
            }
        }
    }
    pdl_trigger();

#pragma unroll
    for (int g = 0; g < CG; g++) {
        float* orow = out + (((size_t)(cb + g) * Do + z) * Ho + y) * Wo + x0;
        if constexpr (TX == 2) {
            *reinterpret_cast<float2*>(orow) = unpack2(accp[g][0]);
        } else {
            const float2 a = unpack2(accp[g][0]);
            const float2 b = unpack2(accp[g][1]);
            *reinterpret_cast<float4*>(orow) = make_float4(a.x, a.y, b.x, b.y);
        }
    }
    if (STATS) {
        float acc_f[CG][TX];
#pragma unroll
        for (int g = 0; g < CG; g++)
#pragma unroll
            for (int k = 0; k < TX / 2; k++) {
                const float2 a = unpack2(accp[g][k]);
                acc_f[g][2 * k] = a.x; acc_f[g][2 * k + 1] = a.y;
            }
        stats_epilogue<CG, TX>(acc_f, part, cb, tid, nthr);
    }
}

// ---------------------------------------------------------------------------
// Stride-2 transposed conv, packed y-pair tile, TX in {4,8}.
// CHUNKED weight staging (<=32 input channels per chunk) — R11 form.
// Weight pairs via LDS.128.
// ---------------------------------------------------------------------------
template <int CG, int TX, bool STATS>
__global__ void tconv_kernel(
        const float* __restrict__ in, const float* __restrict__ wt,
        const float2* __restrict__ coef,
        float* __restrict__ out, double2* __restrict__ part,
        int Cin, int Di, int Hi, int Wi) {
    static_assert(TX == 4 || TX == 8, "tconv needs TX in {4,8}");
    const int Do = 2 * Di, Ho = 2 * Hi, Wo = 2 * Wi;
    extern __shared__ __align__(16) float2 sw2[];
    const int cb   = blockIdx.z * CG;
    const int tid  = threadIdx.y * blockDim.x + threadIdx.x;
    const int nthr = blockDim.x * blockDim.y;

    const int x0 = threadIdx.x * TX;
    const int i0 = x0 >> 1;
    const int yp = blockIdx.x * blockDim.y + threadIdx.y;
    const int z  = blockIdx.y;

    ull accpE[CG][TX / 2], accpO[CG][TX / 2];
#pragma unroll
    for (int g = 0; g < CG; g++)
#pragma unroll
        for (int k = 0; k < TX / 2; k++) { accpE[g][k] = 0ull; accpO[g][k] = 0ull; }

    const bool hb = (yp + 1 < Hi);
    const bool xe = (i0 + TX / 2 < Wi);

    for (int c0 = 0; c0 < Cin; c0 += 32) {
        const int chunk = (Cin - c0 < 32) ? (Cin - c0) : 32;
        __syncthreads();
        // stage transformed weight pairs: 6 float2 per (g, cl, kd)
        for (int i = tid; i < CG * chunk * 3; i += nthr) {
            const int g   = i / (chunk * 3);
            const int rem = i - g * (chunk * 3);
            const int cl  = rem / 3;
            const int kd  = rem - cl * 3;
            const float* w = wt + ((size_t)(cb + g) * Cin + c0 + cl) * 27 + kd * 9;
            float2* p = sw2 + (size_t)i * 6;
            p[0] = make_float2(w[4], w[3]);   // (wa1, wa0)  kh=1
            p[1] = make_float2(0.f,  w[5]);   // (0,   wa2)
            p[2] = make_float2(w[1], w[0]);   // (wb1, wb0)  kh=0
            p[3] = make_float2(w[7], w[6]);   // (wc1, wc0)  kh=2
            p[4] = make_float2(0.f,  w[2]);   // (0,   wb2)
            p[5] = make_float2(0.f,  w[8]);   // (0,   wc2)
        }
        __syncthreads();
        if (c0 == 0) pdl_sync();   // input/coef needed from here on

        for (int cl = 0; cl < chunk; cl++) {
            const float* inc = in + (size_t)(c0 + cl) * Di * Hi * Wi;
            const float2 cf = coef[c0 + cl];
#pragma unroll
            for (int kd = 0; kd < 3; kd++) {
                const int dz = z - 1 + kd;
                if (dz < 0 || (dz & 1)) continue;
                const int iz = dz >> 1;
                if (iz >= Di) continue;

                const float* prow = inc + ((size_t)iz * Hi + yp) * Wi;
                float r[TX / 2 + 1], s[TX / 2 + 1];
                if constexpr (TX == 8) {
                    const float4 v = *reinterpret_cast<const float4*>(prow + i0);
                    r[0] = bnr(v.x, cf); r[1] = bnr(v.y, cf);
                    r[2] = bnr(v.z, cf); r[3] = bnr(v.w, cf);
                    r[4] = xe ? bnr(prow[i0 + 4], cf) : 0.f;
                } else {
                    const float2 v = *reinterpret_cast<const float2*>(prow + i0);
                    r[0] = bnr(v.x, cf); r[1] = bnr(v.y, cf);
                    r[2] = xe ? bnr(prow[i0 + 2], cf) : 0.f;
                }
                if (hb) {
                    const float* qrow = prow + Wi;
                    if constexpr (TX == 8) {
                        const float4 u = *reinterpret_cast<const float4*>(qrow + i0);
                        s[0] = bnr(u.x, cf); s[1] = bnr(u.y, cf);
                        s[2] = bnr(u.z, cf); s[3] = bnr(u.w, cf);
                        s[4] = xe ? bnr(qrow[i0 + 4], cf) : 0.f;
                    } else {
                        const float2 u = *reinterpret_cast<const float2*>(qrow + i0);
                        s[0] = bnr(u.x, cf); s[1] = bnr(u.y, cf);
                        s[2] = xe ? bnr(qrow[i0 + 2], cf) : 0.f;
                    }
                } else {
#pragma unroll
                    for (int e = 0; e <= TX / 2; e++) s[e] = 0.f;
                }
                ull rb[TX / 2 + 1], sb[TX / 2 + 1];
#pragma unroll
                for (int e = 0; e <= TX / 2; e++) {
                    rb[e] = pack2(r[e], r[e]);
                    sb[e] = pack2(s[e], s[e]);
                }
#pragma unroll
                for (int g = 0; g < CG; g++) {
                    const float2* p = sw2 + ((size_t)(g * chunk + cl) * 3 + kd) * 6;
                    ull p0, p1; ld128(p,     p0, p1);
                    ull p2, p3; ld128(p + 2, p2, p3);
                    ull p4, p5; ld128(p + 4, p4, p5);
#pragma unroll
                    for (int e = 0; e < TX / 2; e++) {
                        accpE[g][e] = fma2(rb[e], p0, fma2(rb[e + 1], p1, accpE[g][e]));
                        accpO[g][e] = fma2(rb[e], p2,
                                      fma2(sb[e], p3,
                                      fma2(rb[e + 1], p4,
                                      fma2(sb[e + 1], p5, accpO[g][e]))));
                    }
                }
            }
        }
    }
    pdl_trigger();

#pragma unroll
    for (int g = 0; g < CG; g++) {
        float* erow = out + (((size_t)(cb + g) * Do + z) * Ho + 2 * yp) * Wo + x0;
        float* orow = erow + Wo;
#pragma unroll
        for (int k = 0; k < TX / 2; k += 2) {
            const float2 a = unpack2(accpE[g][k]);
            const float2 b = unpack2(accpE[g][k + 1]);
            *reinterpret_cast<float4*>(erow + 2 * k) = make_float4(a.x, a.y, b.x, b.y);
            const float2 c = unpack2(accpO[g][k]);
            const float2 d = unpack2(accpO[g][k + 1]);
            *reinterpret_cast<float4*>(orow + 2 * k) = make_float4(c.x, c.y, d.x, d.y);
        }
    }
    if (STATS) {
        float acc_f[CG][2 * TX];
#pragma unroll
        for (int g = 0; g < CG; g++)
#pragma unroll
            for (int k = 0; k < TX / 2; k++) {
                const float2 a = unpack2(accpE[g][k]);
                const float2 b = unpack2(accpO[g][k]);
                acc_f[g][2 * k]          = a.x;
                acc_f[g][2 * k + 1]      = a.y;
                acc_f[g][TX + 2 * k]     = b.x;
                acc_f[g][TX + 2 * k + 1] = b.y;
            }
        stats_epilogue<CG, 2 * TX>(acc_f, part, cb, tid, nthr);
    }
}

// ---------------------------------------------------------------------------
// BN finalize: partials -> per-channel (a, b) coefficients.
// Syncs at entry, then triggers (R11 order).
// ---------------------------------------------------------------------------
__global__ void bn_finalize(const double2* __restrict__ part,
                            float2* __restrict__ coef,
                            const float* __restrict__ gam,
                            const float* __restrict__ bet,
                            int P, int V, float eps) {
    pdl_sync();
    pdl_trigger();
    const int c = blockIdx.x;
    double s = 0.0, q = 0.0;
    for (int i = threadIdx.x; i < P; i += 256) {
        const double2 pp = part[(size_t)c * PMAX_ + i];
        s += pp.x; q += pp.y;
    }
    __shared__ double ss[256], sq[256];
    ss[threadIdx.x] = s; sq[threadIdx.x] = q;
    __syncthreads();
    for (int o = 128; o > 0; o >>= 1) {
        if (threadIdx.x < o) {
            ss[threadIdx.x] += ss[threadIdx.x + o];
            sq[threadIdx.x] += sq[threadIdx.x + o];
        }
        __syncthreads();
    }
    if (threadIdx.x == 0) {
        const double mean = ss[0] / V;
        const double var  = sq[0] / V - mean * mean;
        const float inv_std = (float)(1.0 / sqrt(var + (double)eps));
        const float a = inv_std * gam[c];
        const float b = fmaf(-(float)mean, a, bet[c]);
        coef[c] = make_float2(a, b);
    }
}

// ---------------------------------------------------------------------------
// Host orchestration — all launches via cudaLaunchKernelEx with PDL.
// ---------------------------------------------------------------------------
extern "C" void kernel_launch(void* const* d_in, const int* in_sizes, int n_in,
                              void* d_out, int out_size) {
    (void)in_sizes; (void)n_in; (void)out_size;

    const float* x     = (const float*)d_in[0];
    const float* w0    = (const float*)d_in[1];
    const float* g0    = (const float*)d_in[2];
    const float* b0    = (const float*)d_in[3];
    const float* w1    = (const float*)d_in[4];
    const float* g1    = (const float*)d_in[5];
    const float* b1    = (const float*)d_in[6];
    const float* w2    = (const float*)d_in[7];
    const float* g2    = (const float*)d_in[8];
    const float* b2    = (const float*)d_in[9];
    const float* w3    = (const float*)d_in[10];
    const float* g3    = (const float*)d_in[11];
    const float* b3    = (const float*)d_in[12];
    const float* wt3   = (const float*)d_in[13];
    const float* gt3   = (const float*)d_in[14];
    const float* bt3   = (const float*)d_in[15];
    const float* wt2   = (const float*)d_in[16];
    const float* gt2   = (const float*)d_in[17];
    const float* bt2   = (const float*)d_in[18];
    const float* wt1   = (const float*)d_in[19];
    const float* gt1   = (const float*)d_in[20];
    const float* bt1   = (const float*)d_in[21];
    const float* w_out = (const float*)d_in[22];

    float *cat0, *cat1, *cat2, *s8;
    double2* part;
    float2 *coef0, *coef1, *coef2, *coefs8;
    cudaGetSymbolAddress((void**)&cat0,   g_cat0);
    cudaGetSymbolAddress((void**)&cat1,   g_cat1);
    cudaGetSymbolAddress((void**)&cat2,   g_cat2);
    cudaGetSymbolAddress((void**)&s8,     g_s8);
    cudaGetSymbolAddress((void**)&part,   g_part);
    cudaGetSymbolAddress((void**)&coef0,  g_coef0);
    cudaGetSymbolAddress((void**)&coef1,  g_coef1);
    cudaGetSymbolAddress((void**)&coef2,  g_coef2);
    cudaGetSymbolAddress((void**)&coefs8, g_coefs8);

    float* s1 = cat0 + (size_t)24 * V0_;
    float* s2 = cat1 + (size_t)32 * V1_;
    float* s4 = cat2 + (size_t)32 * V2_;

    cudaLaunchAttribute pdl_attr[1];
    pdl_attr[0].id = cudaLaunchAttributeProgrammaticStreamSerialization;
    pdl_attr[0].val.programmaticStreamSerializationAllowed = 1;

    auto cfg = [&](dim3 g, dim3 b, size_t smem) {
        cudaLaunchConfig_t c = {};
        c.gridDim = g; c.blockDim = b; c.dynamicSmemBytes = smem;
        c.stream = 0; c.attrs = pdl_attr; c.numAttrs = 1;
        return c;
    };

    // ---- encoder ----
    // conv0: 8->8, 128^3, stride 1 (raw input)
    {
        cudaLaunchConfig_t c = cfg(dim3(16, 128, 1), dim3(16, 8), 8 * 8 * 9 * 4 * 8);
        cudaLaunchKernelEx(&c, conv_s1_kernel<8, 1, 8, true, false>,
            x, w0, (const float2*)nullptr, s1, part, 8, 128, 128, 128);
    }
    {
        cudaLaunchConfig_t c = cfg(dim3(8, 1, 1), dim3(256, 1, 1), 0);
        cudaLaunchKernelEx(&c, bn_finalize,
            (const double2*)part, coef0 + 24, g0, b0, 16 * 128, V0_, 1e-5f);
    }

    // conv1: 8->16, stride 2 -> 64^3
    {
        cudaLaunchConfig_t c = cfg(dim3(8, 64, 2), dim3(16, 8), 8 * 8 * 9 * 4 * 8);
        cudaLaunchKernelEx(&c, conv_s2_kernel<8, 4, true>,
            (const float*)s1, w1, (const float2*)(coef0 + 24), s2, part,
            8, 128, 128, 128, 64, 64, 64);
    }
    {
        cudaLaunchConfig_t c = cfg(dim3(16, 1, 1), dim3(256, 1, 1), 0);
        cudaLaunchKernelEx(&c, bn_finalize,
            (const double2*)part, coef1 + 32, g1, b1, 8 * 64, V1_, 1e-5f);
    }

    // conv2: 16->32, stride 2 -> 32^3 (CG=4)
    {
        cudaLaunchConfig_t c = cfg(dim3(4, 32, 8), dim3(8, 8), 4 * 16 * 9 * 4 * 8);
        cudaLaunchKernelEx(&c, conv_s2_kernel<4, 4, true>,
            (const float*)s2, w2, (const float2*)(coef1 + 32), s4, part,
            16, 64, 64, 64, 32, 32, 32);
    }
    {
        cudaLaunchConfig_t c = cfg(dim3(32, 1, 1), dim3(256, 1, 1), 0);
        cudaLaunchKernelEx(&c, bn_finalize,
            (const double2*)part, coef2 + 32, g2, b2, 4 * 32, V2_, 1e-5f);
    }

    // conv3: 32->64, stride 2 -> 16^3 (CG=2, TX=2)
    {
        cudaLaunchConfig_t c = cfg(dim3(1, 16, 32), dim3(8, 16), 2 * 32 * 9 * 4 * 8);
        cudaLaunchKernelEx(&c, conv_s2_kernel<2, 2, true>,
            (const float*)s4, w3, (const float2*)(coef2 + 32), s8, part,
            32, 32, 32, 32, 16, 16, 16);
    }
    {
        cudaLaunchConfig_t c = cfg(dim3(64, 1, 1), dim3(256, 1, 1), 0);
        cudaLaunchKernelEx(&c, bn_finalize,
            (const double2*)part, coefs8, g3, b3, 1 * 16, V3_, 1e-5f);
    }

    // ---- decoder ----  (tconv smem: CG*32*3*6 float2)
    // tconv3: 64->32, 16^3 -> 32^3 (CG=2, TX=4)
    {
        cudaLaunchConfig_t c = cfg(dim3(2, 32, 16), dim3(8, 8), 2 * 32 * 3 * 6 * 8);
        cudaLaunchKernelEx(&c, tconv_kernel<2, 4, true>,
            (const float*)s8, wt3, (const float2*)coefs8, cat2, part,
            64, 16, 16, 16);
    }
    {
        cudaLaunchConfig_t c = cfg(dim3(32, 1, 1), dim3(256, 1, 1), 0);
        cudaLaunchKernelEx(&c, bn_finalize,
            (const double2*)part, coef2, gt3, bt3, 2 * 32, V2_, 1e-5f);
    }

    // tconv2: 64->32, 32^3 -> 64^3
    {
        cudaLaunchConfig_t c = cfg(dim3(2, 64, 8), dim3(8, 16), 4 * 32 * 3 * 6 * 8);
        cudaLaunchKernelEx(&c, tconv_kernel<4, 8, true>,
            (const float*)cat2, wt2, (const float2*)coef2, cat1, part,
            64, 32, 32, 32);
    }
    {
        cudaLaunchConfig_t c = cfg(dim3(32, 1, 1), dim3(256, 1, 1), 0);
        cudaLaunchKernelEx(&c, bn_finalize,
            (const double2*)part, coef1, gt2, bt2, 2 * 64, V1_, 1e-5f);
    }

    // tconv1: 48->24, 64^3 -> 128^3
    {
        cudaLaunchConfig_t c = cfg(dim3(8, 128, 6), dim3(16, 8), 4 * 32 * 3 * 6 * 8);
        cudaLaunchKernelEx(&c, tconv_kernel<4, 8, true>,
            (const float*)cat1, wt1, (const float2*)coef1, cat0, part,
            48, 64, 64, 64);
    }
    {
        cudaLaunchConfig_t c = cfg(dim3(24, 1, 1), dim3(256, 1, 1), 0);
        cudaLaunchKernelEx(&c, bn_finalize,
            (const double2*)part, coef0, gt1, bt1, 8 * 128, V0_, 1e-5f);
    }

    // conv_out: 32->2, 128^3, stride 1, TZ=2, folded BN on cat0 loads
    {
        cudaLaunchConfig_t c = cfg(dim3(16, 64, 1), dim3(16, 8), 2 * 32 * 9 * 4 * 8);
        cudaLaunchKernelEx(&c, conv_s1_kernel<2, 2, 8, false, true>,
            (const float*)cat0, w_out, (const float2*)coef0, (float*)d_out,
            (double2*)nullptr, 32, 128, 128, 128);
    }
}

// round 16
// speedup vs baseline: 1.1807x; 1.0198x over previous
#include <cuda_runtime.h>
#include <cstdint>
#include <math.h>

// ---------------------------------------------------------------------------
// UNet4LMCD round 15: R14 champion + ONE knob:
//   tconv_kernel gets __launch_bounds__(128, 5) -> regs capped ~102,
//   5 blocks/SM instead of 4 (+25% warps) with zero added issue slots.
// Everything else byte-identical to the confirmed 1741.9us baseline.
// ---------------------------------------------------------------------------

#define V0_ (128*128*128)
#define V1_ (64*64*64)
#define V2_ (32*32*32)
#define V3_ (16*16*16)
#define PMAX_ 2048

typedef unsigned long long ull;

__device__ float   g_s8  [64 * V3_];
__device__ float   g_cat2[64 * V2_];          // [tconv3 out (32) | s4 (32)]
__device__ float   g_cat1[48 * V1_];          // [tconv2 out (32) | s2 (16)]
__device__ float   g_cat0[32u * V0_];         // [tconv1 out (24) | s1 (8)]
__device__ double2 g_part[64 * PMAX_];
__device__ float2  g_coef0[32];
__device__ float2  g_coef1[48];
__device__ float2  g_coef2[64];
__device__ float2  g_coefs8[64];

// ---- PDL device helpers -----------------------------------------------------
__device__ __forceinline__ void pdl_sync()    { cudaGridDependencySynchronize(); }
__device__ __forceinline__ void pdl_trigger() { cudaTriggerProgrammaticLaunchCompletion(); }

// ---- packed f32x2 helpers --------------------------------------------------
__device__ __forceinline__ ull pack2(float lo, float hi) {
    ull r;
    asm("mov.b64 %0, {%1, %2};" : "=l"(r) : "f"(lo), "f"(hi));
    return r;
}
__device__ __forceinline__ ull fma2(ull a, ull b, ull c) {
    ull d;
    asm("fma.rn.f32x2 %0, %1, %2, %3;" : "=l"(d) : "l"(a), "l"(b), "l"(c));
    return d;
}
__device__ __forceinline__ float2 unpack2(ull v) {
    float2 f;
    asm("mov.b64 {%0, %1}, %2;" : "=f"(f.x), "=f"(f.y) : "l"(v));
    return f;
}
__device__ __forceinline__ ull ld64(const float2* p) {
    return *reinterpret_cast<const ull*>(p);
}
__device__ __forceinline__ void ld128(const float2* p, ull& a, ull& b) {
    const ulonglong2 v = *reinterpret_cast<const ulonglong2*>(p);
    a = v.x; b = v.y;
}
__device__ __forceinline__ float bnr(float v, float2 c) {
    return fmaxf(fmaf(v, c.x, c.y), 0.f);
}

// ---------------------------------------------------------------------------
// Fused BN-stats epilogue over flattened accumulators acc[CG][NT].
// ---------------------------------------------------------------------------
template <int CG, int NT>
__device__ __forceinline__ void stats_epilogue(const float (*acc)[NT],
                                               double2* __restrict__ part,
                                               int cb, int tid, int nthr) {
    float s[CG], q[CG];
#pragma unroll
    for (int g = 0; g < CG; g++) {
        float ss = 0.f, qq = 0.f;
#pragma unroll
        for (int t = 0; t < NT; t++) {
            ss += acc[g][t];
            qq = fmaf(acc[g][t], acc[g][t], qq);
        }
        s[g] = ss; q[g] = qq;
    }
#pragma unroll
    for (int o = 16; o > 0; o >>= 1) {
#pragma unroll
        for (int g = 0; g < CG; g++) {
            s[g] += __shfl_down_sync(0xffffffffu, s[g], o);
            q[g] += __shfl_down_sync(0xffffffffu, q[g], o);
        }
    }
    __shared__ float2 red[CG][8];
    const int wid = tid >> 5, lane = tid & 31;
    if (lane == 0) {
#pragma unroll
        for (int g = 0; g < CG; g++) red[g][wid] = make_float2(s[g], q[g]);
    }
    __syncthreads();
    const int nw = nthr >> 5;
    if (tid < CG) {
        double ds = 0.0, dq = 0.0;
        for (int w = 0; w < nw; w++) {
            ds += (double)red[tid][w].x;
            dq += (double)red[tid][w].y;
        }
        const int pidx = blockIdx.x + gridDim.x * blockIdx.y;
        part[(size_t)(cb + tid) * PMAX_ + pidx] = make_double2(ds, dq);
    }
}

// ---------------------------------------------------------------------------
// Stride-1 3x3x3 conv, packed: CG x TZ x TX(=8). Padded weight layout:
// 4 float2 per (g,ci,kd,kh) triplet -> (w0,w1) via LDS.128, w2 via LDS.64.
// ---------------------------------------------------------------------------
template <int CG, int TZ, int TX, bool STATS, bool APPLY>
__global__ void __launch_bounds__(128) conv_s1_kernel(
        const float* __restrict__ in, const float* __restrict__ wt,
        const float2* __restrict__ coef,
        float* __restrict__ out, double2* __restrict__ part,
        int Cin, int D, int H, int W) {
    static_assert(TX == 8, "conv_s1 needs TX==8");
    extern __shared__ __align__(16) float2 sw2[];
    const int cb   = blockIdx.z * CG;
    const int tid  = threadIdx.y * blockDim.x + threadIdx.x;
    const int nthr = blockDim.x * blockDim.y;
    for (int i = tid; i < CG * Cin * 27; i += nthr) {
        const float w = wt[(size_t)cb * Cin * 27 + i];
        const int tri = i / 3, t = i - tri * 3;
        sw2[tri * 4 + t] = make_float2(w, w);
    }
    __syncthreads();
    pdl_sync();                 // predecessor data (in, coef) needed below

    const int x0 = threadIdx.x * TX;
    const int y  = blockIdx.x * blockDim.y + threadIdx.y;
    const int z0 = blockIdx.y * TZ;

    ull accp[CG][TZ][TX / 2];
#pragma unroll
    for (int g = 0; g < CG; g++)
#pragma unroll
        for (int zz = 0; zz < TZ; zz++)
#pragma unroll
            for (int k = 0; k < TX / 2; k++) accp[g][zz][k] = 0ull;

    for (int ci = 0; ci < Cin; ci++) {
        const float* inc = in + (size_t)ci * D * H * W;
        float2 cf = APPLY ? coef[ci] : make_float2(1.f, 0.f);
#pragma unroll
        for (int pz = 0; pz < TZ + 2; pz++) {
            const int iz = z0 - 1 + pz;
            if (iz < 0 || iz >= D) continue;
#pragma unroll
            for (int kh = 0; kh < 3; kh++) {
                const int iy = y + kh - 1;
                if (iy < 0 || iy >= H) continue;
                const float* row = inc + ((size_t)iz * H + iy) * W;
                float r[TX + 2];
                const float4 v0 = *reinterpret_cast<const float4*>(row + x0);
                const float4 v1 = *reinterpret_cast<const float4*>(row + x0 + 4);
                if (APPLY) {
                    r[0] = (x0 > 0) ? bnr(row[x0 - 1], cf) : 0.f;
                    r[1] = bnr(v0.x, cf); r[2] = bnr(v0.y, cf);
                    r[3] = bnr(v0.z, cf); r[4] = bnr(v0.w, cf);
                    r[5] = bnr(v1.x, cf); r[6] = bnr(v1.y, cf);
                    r[7] = bnr(v1.z, cf); r[8] = bnr(v1.w, cf);
                    r[9] = (x0 + TX < W) ? bnr(row[x0 + TX], cf) : 0.f;
                } else {
                    r[0] = (x0 > 0) ? row[x0 - 1] : 0.f;
                    r[1] = v0.x; r[2] = v0.y; r[3] = v0.z; r[4] = v0.w;
                    r[5] = v1.x; r[6] = v1.y; r[7] = v1.z; r[8] = v1.w;
                    r[9] = (x0 + TX < W) ? row[x0 + TX] : 0.f;
                }
                // pair registers: E_k = (r[2k], r[2k+1]), O_k = (r[2k+1], r[2k+2])
                ull E[TX / 2 + 1], O[TX / 2];
#pragma unroll
                for (int k = 0; k <= TX / 2; k++) E[k] = pack2(r[2 * k], r[2 * k + 1]);
#pragma unroll
                for (int k = 0; k < TX / 2; k++)  O[k] = pack2(r[2 * k + 1], r[2 * k + 2]);
#pragma unroll
                for (int zz = 0; zz < TZ; zz++) {
                    const int kd = iz - (z0 + zz) + 1;
                    if (kd < 0 || kd > 2) continue;
#pragma unroll
                    for (int g = 0; g < CG; g++) {
                        const float2* wp = sw2 +
                            (((size_t)g * Cin + ci) * 9 + kd * 3 + kh) * 4;
                        ull w0, w1; ld128(wp, w0, w1);
                        const ull w2 = ld64(wp + 2);
#pragma unroll
                        for (int k = 0; k < TX / 2; k++)
                            accp[g][zz][k] = fma2(E[k], w0,
                                             fma2(O[k], w1,
                                             fma2(E[k + 1], w2, accp[g][zz][k])));
                    }
                }
            }
        }
    }
    pdl_trigger();              // successor may launch; epilogue remains

#pragma unroll
    for (int g = 0; g < CG; g++)
#pragma unroll
        for (int zz = 0; zz < TZ; zz++) {
            float* orow = out + (((size_t)(cb + g) * D + z0 + zz) * H + y) * W + x0;
#pragma unroll
            for (int k = 0; k < TX / 2; k += 2) {
                const float2 a = unpack2(accp[g][zz][k]);
                const float2 b = unpack2(accp[g][zz][k + 1]);
                *reinterpret_cast<float4*>(orow + 2 * k) = make_float4(a.x, a.y, b.x, b.y);
            }
        }
    if (STATS) {
        float acc_f[CG][TZ * TX];
#pragma unroll
        for (int g = 0; g < CG; g++)
#pragma unroll
            for (int zz = 0; zz < TZ; zz++)
#pragma unroll
                for (int k = 0; k < TX / 2; k++) {
                    const float2 a = unpack2(accp[g][zz][k]);
                    acc_f[g][zz * TX + 2 * k]     = a.x;
                    acc_f[g][zz * TX + 2 * k + 1] = a.y;
                }
        stats_epilogue<CG, TZ * TX>(acc_f, part, cb, tid, nthr);
    }
}

// ---------------------------------------------------------------------------
// Stride-2 3x3x3 conv, packed: CG x TX (2 or 4). Padded weight layout.
// ---------------------------------------------------------------------------
template <int CG, int TX, bool STATS>
__global__ void conv_s2_kernel(
        const float* __restrict__ in, const float* __restrict__ wt,
        const float2* __restrict__ coef,
        float* __restrict__ out, double2* __restrict__ part,
        int Cin, int Di, int Hi, int Wi, int Do, int Ho, int Wo) {
    static_assert(TX == 2 || TX == 4, "conv_s2 needs TX in {2,4}");
    extern __shared__ __align__(16) float2 sw2[];
    const int cb   = blockIdx.z * CG;
    const int tid  = threadIdx.y * blockDim.x + threadIdx.x;
    const int nthr = blockDim.x * blockDim.y;
    for (int i = tid; i < CG * Cin * 27; i += nthr) {
        const float w = wt[(size_t)cb * Cin * 27 + i];
        const int tri = i / 3, t = i - tri * 3;
        sw2[tri * 4 + t] = make_float2(w, w);
    }
    __syncthreads();
    pdl_sync();

    const int x0 = threadIdx.x * TX;
    const int bx = 2 * x0;
    const int y  = blockIdx.x * blockDim.y + threadIdx.y;
    const int z  = blockIdx.y;

    ull accp[CG][TX / 2];
#pragma unroll
    for (int g = 0; g < CG; g++)
#pragma unroll
        for (int k = 0; k < TX / 2; k++) accp[g][k] = 0ull;

    for (int ci = 0; ci < Cin; ci++) {
        const float* inc = in + (size_t)ci * Di * Hi * Wi;
        const float2 cf = coef[ci];
#pragma unroll
        for (int kd = 0; kd < 3; kd++) {
            const int iz = 2 * z + kd - 1;
            if (iz < 0 || iz >= Di) continue;
#pragma unroll
            for (int kh = 0; kh < 3; kh++) {
                const int iy = 2 * y + kh - 1;
                if (iy < 0 || iy >= Hi) continue;
                const float* row = inc + ((size_t)iz * Hi + iy) * Wi;
                float rr[2 * TX + 2];
                rr[0] = (bx > 0) ? bnr(row[bx - 1], cf) : 0.f;
#pragma unroll
                for (int q = 0; q < TX / 2; q++) {
                    const float4 v = *reinterpret_cast<const float4*>(row + bx + 4 * q);
                    rr[4 * q + 1] = bnr(v.x, cf); rr[4 * q + 2] = bnr(v.y, cf);
                    rr[4 * q + 3] = bnr(v.z, cf); rr[4 * q + 4] = bnr(v.w, cf);
                }
                rr[2 * TX + 1] = (bx + 2 * TX < Wi) ? bnr(row[bx + 2 * TX], cf) : 0.f;
                ull M[3][TX / 2];
#pragma unroll
                for (int j = 0; j < 3; j++)
#pragma unroll
                    for (int k = 0; k < TX / 2; k++)
                        M[j][k] = pack2(rr[4 * k + j], rr[4 * k + j + 2]);
#pragma unroll
                for (int g = 0; g < CG; g++) {
                    const float2* wp = sw2 +
                        (((size_t)g * Cin + ci) * 9 + kd * 3 + kh) * 4;
                    ull w0, w1; ld128(wp, w0, w1);
                    const ull w2 = ld64(wp + 2);
#pragma unroll
                    for (int k = 0; k < TX / 2; k++)
                        accp[g][k] = fma2(M[0][k], w0,
                                     fma2(M[1][k], w1,
                                     fma2(M[2][k], w2, accp[g][k])));
                }
            }
        }
    }
    pdl_trigger();

#pragma unroll
    for (int g = 0; g < CG; g++) {
        float* orow = out + (((size_t)(cb + g) * Do + z) * Ho + y) * Wo + x0;
        if constexpr (TX == 2) {
            *reinterpret_cast<float2*>(orow) = unpack2(accp[g][0]);
        } else {
            const float2 a = unpack2(accp[g][0]);
            const float2 b = unpack2(accp[g][1]);
            *reinterpret_cast<float4*>(orow) = make_float4(a.x, a.y, b.x, b.y);
        }
    }
    if (STATS) {
        float acc_f[CG][TX];
#pragma unroll
        for (int g = 0; g < CG; g++)
#pragma unroll
            for (int k = 0; k < TX / 2; k++) {
                const float2 a = unpack2(accp[g][k]);
                acc_f[g][2 * k] = a.x; acc_f[g][2 * k + 1] = a.y;
            }
        stats_epilogue<CG, TX>(acc_f, part, cb, tid, nthr);
    }
}

// ---------------------------------------------------------------------------
// Stride-2 transposed conv, packed y-pair tile, TX in {4,8}.
// CHUNKED weight staging (<=32 input channels per chunk) — R11/R14 form.
// __launch_bounds__(128, 5): cap regs ~102 -> 5 blocks/SM (was 4).
// ---------------------------------------------------------------------------
template <int CG, int TX, bool STATS>
__global__ void __launch_bounds__(128, 5) tconv_kernel(
        const float* __restrict__ in, const float* __restrict__ wt,
        const float2* __restrict__ coef,
        float* __restrict__ out, double2* __restrict__ part,
        int Cin, int Di, int Hi, int Wi) {
    static_assert(TX == 4 || TX == 8, "tconv needs TX in {4,8}");
    const int Do = 2 * Di, Ho = 2 * Hi, Wo = 2 * Wi;
    extern __shared__ __align__(16) float2 sw2[];
    const int cb   = blockIdx.z * CG;
    const int tid  = threadIdx.y * blockDim.x + threadIdx.x;
    const int nthr = blockDim.x * blockDim.y;

    const int x0 = threadIdx.x * TX;
    const int i0 = x0 >> 1;
    const int yp = blockIdx.x * blockDim.y + threadIdx.y;
    const int z  = blockIdx.y;

    ull accpE[CG][TX / 2], accpO[CG][TX / 2];
#pragma unroll
    for (int g = 0; g < CG; g++)
#pragma unroll
        for (int k = 0; k < TX / 2; k++) { accpE[g][k] = 0ull; accpO[g][k] = 0ull; }

    const bool hb = (yp + 1 < Hi);
    const bool xe = (i0 + TX / 2 < Wi);

    for (int c0 = 0; c0 < Cin; c0 += 32) {
        const int chunk = (Cin - c0 < 32) ? (Cin - c0) : 32;
        __syncthreads();
        // stage transformed weight pairs: 6 float2 per (g, cl, kd)
        for (int i = tid; i < CG * chunk * 3; i += nthr) {
            const int g   = i / (chunk * 3);
            const int rem = i - g * (chunk * 3);
            const int cl  = rem / 3;
            const int kd  = rem - cl * 3;
            const float* w = wt + ((size_t)(cb + g) * Cin + c0 + cl) * 27 + kd * 9;
            float2* p = sw2 + (size_t)i * 6;
            p[0] = make_float2(w[4], w[3]);   // (wa1, wa0)  kh=1
            p[1] = make_float2(0.f,  w[5]);   // (0,   wa2)
            p[2] = make_float2(w[1], w[0]);   // (wb1, wb0)  kh=0
            p[3] = make_float2(w[7], w[6]);   // (wc1, wc0)  kh=2
            p[4] = make_float2(0.f,  w[2]);   // (0,   wb2)
            p[5] = make_float2(0.f,  w[8]);   // (0,   wc2)
        }
        __syncthreads();
        if (c0 == 0) pdl_sync();   // input/coef needed from here on

        for (int cl = 0; cl < chunk; cl++) {
            const float* inc = in + (size_t)(c0 + cl) * Di * Hi * Wi;
            const float2 cf = coef[c0 + cl];
#pragma unroll
            for (int kd = 0; kd < 3; kd++) {
                const int dz = z - 1 + kd;
                if (dz < 0 || (dz & 1)) continue;
                const int iz = dz >> 1;
                if (iz >= Di) continue;

                const float* prow = inc + ((size_t)iz * Hi + yp) * Wi;
                float r[TX / 2 + 1], s[TX / 2 + 1];
                if constexpr (TX == 8) {
                    const float4 v = *reinterpret_cast<const float4*>(prow + i0);
                    r[0] = bnr(v.x, cf); r[1] = bnr(v.y, cf);
                    r[2] = bnr(v.z, cf); r[3] = bnr(v.w, cf);
                    r[4] = xe ? bnr(prow[i0 + 4], cf) : 0.f;
                } else {
                    const float2 v = *reinterpret_cast<const float2*>(prow + i0);
                    r[0] = bnr(v.x, cf); r[1] = bnr(v.y, cf);
                    r[2] = xe ? bnr(prow[i0 + 2], cf) : 0.f;
                }
                if (hb) {
                    const float* qrow = prow + Wi;
                    if constexpr (TX == 8) {
                        const float4 u = *reinterpret_cast<const float4*>(qrow + i0);
                        s[0] = bnr(u.x, cf); s[1] = bnr(u.y, cf);
                        s[2] = bnr(u.z, cf); s[3] = bnr(u.w, cf);
                        s[4] = xe ? bnr(qrow[i0 + 4], cf) : 0.f;
                    } else {
                        const float2 u = *reinterpret_cast<const float2*>(qrow + i0);
                        s[0] = bnr(u.x, cf); s[1] = bnr(u.y, cf);
                        s[2] = xe ? bnr(qrow[i0 + 2], cf) : 0.f;
                    }
                } else {
#pragma unroll
                    for (int e = 0; e <= TX / 2; e++) s[e] = 0.f;
                }
                ull rb[TX / 2 + 1], sb[TX / 2 + 1];
#pragma unroll
                for (int e = 0; e <= TX / 2; e++) {
                    rb[e] = pack2(r[e], r[e]);
                    sb[e] = pack2(s[e], s[e]);
                }
#pragma unroll
                for (int g = 0; g < CG; g++) {
                    const float2* p = sw2 + ((size_t)(g * chunk + cl) * 3 + kd) * 6;
                    ull p0, p1; ld128(p,     p0, p1);
                    ull p2, p3; ld128(p + 2, p2, p3);
                    ull p4, p5; ld128(p + 4, p4, p5);
#pragma unroll
                    for (int e = 0; e < TX / 2; e++) {
                        accpE[g][e] = fma2(rb[e], p0, fma2(rb[e + 1], p1, accpE[g][e]));
                        accpO[g][e] = fma2(rb[e], p2,
                                      fma2(sb[e], p3,
                                      fma2(rb[e + 1], p4,
                                      fma2(sb[e + 1], p5, accpO[g][e]))));
                    }
                }
            }
        }
    }
    pdl_trigger();

#pragma unroll
    for (int g = 0; g < CG; g++) {
        float* erow = out + (((size_t)(cb + g) * Do + z) * Ho + 2 * yp) * Wo + x0;
        float* orow = erow + Wo;
#pragma unroll
        for (int k = 0; k < TX / 2; k += 2) {
            const float2 a = unpack2(accpE[g][k]);
            const float2 b = unpack2(accpE[g][k + 1]);
            *reinterpret_cast<float4*>(erow + 2 * k) = make_float4(a.x, a.y, b.x, b.y);
            const float2 c = unpack2(accpO[g][k]);
            const float2 d = unpack2(accpO[g][k + 1]);
            *reinterpret_cast<float4*>(orow + 2 * k) = make_float4(c.x, c.y, d.x, d.y);
        }
    }
    if (STATS) {
        float acc_f[CG][2 * TX];
#pragma unroll
        for (int g = 0; g < CG; g++)
#pragma unroll
            for (int k = 0; k < TX / 2; k++) {
                const float2 a = unpack2(accpE[g][k]);
                const float2 b = unpack2(accpO[g][k]);
                acc_f[g][2 * k]          = a.x;
                acc_f[g][2 * k + 1]      = a.y;
                acc_f[g][TX + 2 * k]     = b.x;
                acc_f[g][TX + 2 * k + 1] = b.y;
            }
        stats_epilogue<CG, 2 * TX>(acc_f, part, cb, tid, nthr);
    }
}

// ---------------------------------------------------------------------------
// BN finalize: partials -> per-channel (a, b) coefficients.
// Syncs at entry, then triggers (R11/R14 order).
// ---------------------------------------------------------------------------
__global__ void bn_finalize(const double2* __restrict__ part,
                            float2* __restrict__ coef,
                            const float* __restrict__ gam,
                            const float* __restrict__ bet,
                            int P, int V, float eps) {
    pdl_sync();
    pdl_trigger();
    const int c = blockIdx.x;
    double s = 0.0, q = 0.0;
    for (int i = threadIdx.x; i < P; i += 256) {
        const double2 pp = part[(size_t)c * PMAX_ + i];
        s += pp.x; q += pp.y;
    }
    __shared__ double ss[256], sq[256];
    ss[threadIdx.x] = s; sq[threadIdx.x] = q;
    __syncthreads();
    for (int o = 128; o > 0; o >>= 1) {
        if (threadIdx.x < o) {
            ss[threadIdx.x] += ss[threadIdx.x + o];
            sq[threadIdx.x] += sq[threadIdx.x + o];
        }
        __syncthreads();
    }
    if (threadIdx.x == 0) {
        const double mean = ss[0] / V;
        const double var  = sq[0] / V - mean * mean;
        const float inv_std = (float)(1.0 / sqrt(var + (double)eps));
        const float a = inv_std * gam[c];
        const float b = fmaf(-(float)mean, a, bet[c]);
        coef[c] = make_float2(a, b);
    }
}

// ---------------------------------------------------------------------------
// Host orchestration — all launches via cudaLaunchKernelEx with PDL.
// ---------------------------------------------------------------------------
extern "C" void kernel_launch(void* const* d_in, const int* in_sizes, int n_in,
                              void* d_out, int out_size) {
    (void)in_sizes; (void)n_in; (void)out_size;

    const float* x     = (const float*)d_in[0];
    const float* w0    = (const float*)d_in[1];
    const float* g0    = (const float*)d_in[2];
    const float* b0    = (const float*)d_in[3];
    const float* w1    = (const float*)d_in[4];
    const float* g1    = (const float*)d_in[5];
    const float* b1    = (const float*)d_in[6];
    const float* w2    = (const float*)d_in[7];
    const float* g2    = (const float*)d_in[8];
    const float* b2    = (const float*)d_in[9];
    const float* w3    = (const float*)d_in[10];
    const float* g3    = (const float*)d_in[11];
    const float* b3    = (const float*)d_in[12];
    const float* wt3   = (const float*)d_in[13];
    const float* gt3   = (const float*)d_in[14];
    const float* bt3   = (const float*)d_in[15];
    const float* wt2   = (const float*)d_in[16];
    const float* gt2   = (const float*)d_in[17];
    const float* bt2   = (const float*)d_in[18];
    const float* wt1   = (const float*)d_in[19];
    const float* gt1   = (const float*)d_in[20];
    const float* bt1   = (const float*)d_in[21];
    const float* w_out = (const float*)d_in[22];

    float *cat0, *cat1, *cat2, *s8;
    double2* part;
    float2 *coef0, *coef1, *coef2, *coefs8;
    cudaGetSymbolAddress((void**)&cat0,   g_cat0);
    cudaGetSymbolAddress((void**)&cat1,   g_cat1);
    cudaGetSymbolAddress((void**)&cat2,   g_cat2);
    cudaGetSymbolAddress((void**)&s8,     g_s8);
    cudaGetSymbolAddress((void**)&part,   g_part);
    cudaGetSymbolAddress((void**)&coef0,  g_coef0);
    cudaGetSymbolAddress((void**)&coef1,  g_coef1);
    cudaGetSymbolAddress((void**)&coef2,  g_coef2);
    cudaGetSymbolAddress((void**)&coefs8, g_coefs8);

    float* s1 = cat0 + (size_t)24 * V0_;
    float* s2 = cat1 + (size_t)32 * V1_;
    float* s4 = cat2 + (size_t)32 * V2_;

    cudaLaunchAttribute pdl_attr[1];
    pdl_attr[0].id = cudaLaunchAttributeProgrammaticStreamSerialization;
    pdl_attr[0].val.programmaticStreamSerializationAllowed = 1;

    auto cfg = [&](dim3 g, dim3 b, size_t smem) {
        cudaLaunchConfig_t c = {};
        c.gridDim = g; c.blockDim = b; c.dynamicSmemBytes = smem;
        c.stream = 0; c.attrs = pdl_attr; c.numAttrs = 1;
        return c;
    };

    // ---- encoder ----
    // conv0: 8->8, 128^3, stride 1 (raw input)
    {
        cudaLaunchConfig_t c = cfg(dim3(16, 128, 1), dim3(16, 8), 8 * 8 * 9 * 4 * 8);
        cudaLaunchKernelEx(&c, conv_s1_kernel<8, 1, 8, true, false>,
            x, w0, (const float2*)nullptr, s1, part, 8, 128, 128, 128);
    }
    {
        cudaLaunchConfig_t c = cfg(dim3(8, 1, 1), dim3(256, 1, 1), 0);
        cudaLaunchKernelEx(&c, bn_finalize,
            (const double2*)part, coef0 + 24, g0, b0, 16 * 128, V0_, 1e-5f);
    }

    // conv1: 8->16, stride 2 -> 64^3
    {
        cudaLaunchConfig_t c = cfg(dim3(8, 64, 2), dim3(16, 8), 8 * 8 * 9 * 4 * 8);
        cudaLaunchKernelEx(&c, conv_s2_kernel<8, 4, true>,
            (const float*)s1, w1, (const float2*)(coef0 + 24), s2, part,
            8, 128, 128, 128, 64, 64, 64);
    }
    {
        cudaLaunchConfig_t c = cfg(dim3(16, 1, 1), dim3(256, 1, 1), 0);
        cudaLaunchKernelEx(&c, bn_finalize,
            (const double2*)part, coef1 + 32, g1, b1, 8 * 64, V1_, 1e-5f);
    }

    // conv2: 16->32, stride 2 -> 32^3 (CG=4)
    {
        cudaLaunchConfig_t c = cfg(dim3(4, 32, 8), dim3(8, 8), 4 * 16 * 9 * 4 * 8);
        cudaLaunchKernelEx(&c, conv_s2_kernel<4, 4, true>,
            (const float*)s2, w2, (const float2*)(coef1 + 32), s4, part,
            16, 64, 64, 64, 32, 32, 32);
    }
    {
        cudaLaunchConfig_t c = cfg(dim3(32, 1, 1), dim3(256, 1, 1), 0);
        cudaLaunchKernelEx(&c, bn_finalize,
            (const double2*)part, coef2 + 32, g2, b2, 4 * 32, V2_, 1e-5f);
    }

    // conv3: 32->64, stride 2 -> 16^3 (CG=2, TX=2)
    {
        cudaLaunchConfig_t c = cfg(dim3(1, 16, 32), dim3(8, 16), 2 * 32 * 9 * 4 * 8);
        cudaLaunchKernelEx(&c, conv_s2_kernel<2, 2, true>,
            (const float*)s4, w3, (const float2*)(coef2 + 32), s8, part,
            32, 32, 32, 32, 16, 16, 16);
    }
    {
        cudaLaunchConfig_t c = cfg(dim3(64, 1, 1), dim3(256, 1, 1), 0);
        cudaLaunchKernelEx(&c, bn_finalize,
            (const double2*)part, coefs8, g3, b3, 1 * 16, V3_, 1e-5f);
    }

    // ---- decoder ----  (tconv smem: CG*32*3*6 float2)
    // tconv3: 64->32, 16^3 -> 32^3 (CG=2, TX=4)
    {
        cudaLaunchConfig_t c = cfg(dim3(2, 32, 16), dim3(8, 8), 2 * 32 * 3 * 6 * 8);
        cudaLaunchKernelEx(&c, tconv_kernel<2, 4, true>,
            (const float*)s8, wt3, (const float2*)coefs8, cat2, part,
            64, 16, 16, 16);
    }
    {
        cudaLaunchConfig_t c = cfg(dim3(32, 1, 1), dim3(256, 1, 1), 0);
        cudaLaunchKernelEx(&c, bn_finalize,
            (const double2*)part, coef2, gt3, bt3, 2 * 32, V2_, 1e-5f);
    }

    // tconv2: 64->32, 32^3 -> 64^3
    {
        cudaLaunchConfig_t c = cfg(dim3(2, 64, 8), dim3(8, 16), 4 * 32 * 3 * 6 * 8);
        cudaLaunchKernelEx(&c, tconv_kernel<4, 8, true>,
            (const float*)cat2, wt2, (const float2*)coef2, cat1, part,
            64, 32, 32, 32);
    }
    {
        cudaLaunchConfig_t c = cfg(dim3(32, 1, 1), dim3(256, 1, 1), 0);
        cudaLaunchKernelEx(&c, bn_finalize,
            (const double2*)part, coef1, gt2, bt2, 2 * 64, V1_, 1e-5f);
    }

    // tconv1: 48->24, 64^3 -> 128^3
    {
        cudaLaunchConfig_t c = cfg(dim3(8, 128, 6), dim3(16, 8), 4 * 32 * 3 * 6 * 8);
        cudaLaunchKernelEx(&c, tconv_kernel<4, 8, true>,
            (const float*)cat1, wt1, (const float2*)coef1, cat0, part,
            48, 64, 64, 64);
    }
    {
        cudaLaunchConfig_t c = cfg(dim3(24, 1, 1), dim3(256, 1, 1), 0);
        cudaLaunchKernelEx(&c, bn_finalize,
            (const double2*)part, coef0, gt1, bt1, 8 * 128, V0_, 1e-5f);
    }

    // conv_out: 32->2, 128^3, stride 1, TZ=2, folded BN on cat0 loads
    {
        cudaLaunchConfig_t c = cfg(dim3(16, 64, 1), dim3(16, 8), 2 * 32 * 9 * 4 * 8);
        cudaLaunchKernelEx(&c, conv_s1_kernel<2, 2, 8, false, true>,
            (const float*)cat0, w_out, (const float2*)coef0, (float*)d_out,
            (double2*)nullptr, 32, 128, 128, 128);
    }
}